// round 2
// baseline (speedup 1.0000x reference)
#include <cuda_runtime.h>
#include <cstdint>
#include <cstddef>

#define D_MODEL 1024
#define N_HEADS 16
#define DK      64
#define BATCH   4
#define SEQ     2048
#define FPQ     65   // pitch for 64-wide tiles
#define FPS     33   // pitch for 32-wide S tile

// Scratch (static device globals — allocation APIs are forbidden)
__device__ float g_qkv[(size_t)BATCH * SEQ * 3 * D_MODEL];   // 96 MB
__device__ float g_attn[(size_t)BATCH * SEQ * D_MODEL];      // 32 MB

// ----------------------------------------------------------------------------
// Tiled SGEMM: C[M,N] = A[M,K] * B[K,N], row-major.
// 128x128 block tile, BK=8, 256 threads, 8x8 micro-tile per thread.
// SRC_GLOBAL: A comes from g_attn. DST_GLOBAL: C goes to g_qkv.
// ----------------------------------------------------------------------------
template <bool SRC_GLOBAL, bool DST_GLOBAL>
__global__ __launch_bounds__(256) void sgemm_kernel(
    const float* __restrict__ Ain, const float* __restrict__ B,
    float* __restrict__ Cout, int M, int N, int K)
{
    const float* A = SRC_GLOBAL ? (const float*)g_attn : Ain;
    float*       C = DST_GLOBAL ? (float*)g_qkv        : Cout;

    __shared__ float As[8][128];   // transposed: As[k][m]
    __shared__ float Bs[8][128];

    const int tid = threadIdx.x;
    const int ty = tid >> 4;        // 0..15
    const int tx = tid & 15;        // 0..15
    const int row0 = blockIdx.y * 128;
    const int col0 = blockIdx.x * 128;

    const int a_r = tid >> 1;            // 0..127
    const int a_c = (tid & 1) * 4;       // 0 or 4
    const int b_r = tid >> 5;            // 0..7
    const int b_c = (tid & 31) * 4;      // 0..124

    const float* Ap = A + (size_t)(row0 + a_r) * K + a_c;
    const float* Bp = B + (size_t)b_r * N + col0 + b_c;

    float acc[8][8];
    #pragma unroll
    for (int i = 0; i < 8; i++)
        #pragma unroll
        for (int j = 0; j < 8; j++) acc[i][j] = 0.f;

    for (int k0 = 0; k0 < K; k0 += 8) {
        float4 av = *(const float4*)(Ap + k0);
        float4 bv = *(const float4*)(Bp + (size_t)k0 * N);
        As[a_c + 0][a_r] = av.x;
        As[a_c + 1][a_r] = av.y;
        As[a_c + 2][a_r] = av.z;
        As[a_c + 3][a_r] = av.w;
        *(float4*)&Bs[b_r][b_c] = bv;
        __syncthreads();

        #pragma unroll
        for (int k = 0; k < 8; k++) {
            float af[8], bf[8];
            #pragma unroll
            for (int i = 0; i < 8; i++) af[i] = As[k][ty * 8 + i];
            #pragma unroll
            for (int j = 0; j < 8; j++) bf[j] = Bs[k][tx * 8 + j];
            #pragma unroll
            for (int i = 0; i < 8; i++)
                #pragma unroll
                for (int j = 0; j < 8; j++)
                    acc[i][j] = fmaf(af[i], bf[j], acc[i][j]);
        }
        __syncthreads();
    }

    float* Cp = C + (size_t)(row0 + ty * 8) * N + col0 + tx * 8;
    #pragma unroll
    for (int i = 0; i < 8; i++) {
        *(float4*)(Cp + (size_t)i * N) =
            make_float4(acc[i][0], acc[i][1], acc[i][2], acc[i][3]);
        *(float4*)(Cp + (size_t)i * N + 4) =
            make_float4(acc[i][4], acc[i][5], acc[i][6], acc[i][7]);
    }
}

// ----------------------------------------------------------------------------
// Flash attention (causal), fp32. One block = 64 queries x one (b,h).
// Reads g_qkv (row layout 3072: [q | k | v], each 16 heads x 64),
// writes g_attn [b, t, h*64+d]. Q pre-scaled by 1/sqrt(64)=0.125.
// Key tiles of 32 keys; online softmax. 256 threads.
// Static shared < 48 KB (no attribute call needed).
// ----------------------------------------------------------------------------
__global__ __launch_bounds__(256) void flash_kernel()
{
    __shared__ float Qs[64 * FPQ];   // 16.6 KB
    __shared__ float Ks[32 * FPQ];   //  8.3 KB
    __shared__ float Vs[32 * FPQ];   //  8.3 KB
    __shared__ float Ss[64 * FPS];   //  8.4 KB
    __shared__ float mrow[64], lrow[64], arow[64];

    const float* qkv = (const float*)g_qkv;
    float*       out = (float*)g_attn;

    const int tid = threadIdx.x;
    const int ty = tid >> 4, tx = tid & 15;   // 16x16
    const int bh = blockIdx.y;
    const int b = bh >> 4, h = bh & 15;
    const int i0 = blockIdx.x * 64;

    const float* base = qkv + (size_t)b * SEQ * 3 * D_MODEL + h * DK;

    // Load Q tile (64x64), scaled
    #pragma unroll
    for (int v = 0; v < 4; v++) {
        int e = v * 1024 + tid * 4;
        int r = e >> 6, c = e & 63;
        float4 q4 = *(const float4*)(base + (size_t)(i0 + r) * (3 * D_MODEL) + c);
        float* dst = Qs + r * FPQ + c;
        dst[0] = q4.x * 0.125f; dst[1] = q4.y * 0.125f;
        dst[2] = q4.z * 0.125f; dst[3] = q4.w * 0.125f;
    }
    if (tid < 64) { mrow[tid] = -1e30f; lrow[tid] = 0.f; }

    float acc[4][4];
    #pragma unroll
    for (int i = 0; i < 4; i++)
        #pragma unroll
        for (int j = 0; j < 4; j++) acc[i][j] = 0.f;

    const int ntiles = 2 * blockIdx.x + 2;   // 32-key tiles covering keys <= i0+63
    for (int j = 0; j < ntiles; j++) {
        const int j0 = j * 32;
        __syncthreads();   // prior iteration done with Ks/Vs/Ss; Q visible (iter 0)

        // Load K and V tiles (32x64 each): 8 floats per thread per tile
        #pragma unroll
        for (int v = 0; v < 2; v++) {
            int e = v * 1024 + tid * 4;
            int r = e >> 6, c = e & 63;
            const float* kp = base + (size_t)(j0 + r) * (3 * D_MODEL) + D_MODEL + c;
            float4 k4 = *(const float4*)kp;
            float4 v4 = *(const float4*)(kp + D_MODEL);
            float* kd = Ks + r * FPQ + c;
            kd[0] = k4.x; kd[1] = k4.y; kd[2] = k4.z; kd[3] = k4.w;
            float* vd = Vs + r * FPQ + c;
            vd[0] = v4.x; vd[1] = v4.y; vd[2] = v4.z; vd[3] = v4.w;
        }
        __syncthreads();

        // S(64x32) = Q * K^T : 4 rows x 2 cols per thread
        float sacc[4][2];
        #pragma unroll
        for (int i = 0; i < 4; i++) { sacc[i][0] = 0.f; sacc[i][1] = 0.f; }

        #pragma unroll 8
        for (int k = 0; k < 64; k++) {
            float qf[4], kf[2];
            #pragma unroll
            for (int i = 0; i < 4; i++) qf[i] = Qs[(ty * 4 + i) * FPQ + k];
            kf[0] = Ks[(tx * 2 + 0) * FPQ + k];
            kf[1] = Ks[(tx * 2 + 1) * FPQ + k];
            #pragma unroll
            for (int i = 0; i < 4; i++) {
                sacc[i][0] = fmaf(qf[i], kf[0], sacc[i][0]);
                sacc[i][1] = fmaf(qf[i], kf[1], sacc[i][1]);
            }
        }

        // Causal mask applies only to the last two tiles (j0 >= i0)
        const bool needMask = (j0 + 31 > i0);
        const int coff = j0 - i0;   // global col = i0 + coff + c_local
        #pragma unroll
        for (int i = 0; i < 4; i++) {
            int r = ty * 4 + i;
            #pragma unroll
            for (int jj = 0; jj < 2; jj++) {
                int c = tx * 2 + jj;
                float s = sacc[i][jj];
                if (needMask && (coff + c > r)) s = -1e9f;
                Ss[r * FPS + c] = s;
            }
        }
        __syncthreads();

        // Online softmax row update (one thread per row)
        if (tid < 64) {
            int r = tid;
            float mold = mrow[r];
            float mx = mold;
            #pragma unroll 8
            for (int c = 0; c < 32; c++) mx = fmaxf(mx, Ss[r * FPS + c]);
            float a = __expf(mold - mx);
            float sum = 0.f;
            #pragma unroll 8
            for (int c = 0; c < 32; c++) {
                float p = __expf(Ss[r * FPS + c] - mx);
                Ss[r * FPS + c] = p;
                sum += p;
            }
            lrow[r] = lrow[r] * a + sum;
            mrow[r] = mx;
            arow[r] = a;
        }
        __syncthreads();

        // Rescale accumulators, then O += P * V (4x4 per thread)
        float al[4];
        #pragma unroll
        for (int i = 0; i < 4; i++) al[i] = arow[ty * 4 + i];
        #pragma unroll
        for (int i = 0; i < 4; i++)
            #pragma unroll
            for (int jj = 0; jj < 4; jj++) acc[i][jj] *= al[i];

        #pragma unroll 8
        for (int c = 0; c < 32; c++) {
            float pf[4], vf[4];
            #pragma unroll
            for (int i = 0; i < 4; i++)  pf[i]  = Ss[(ty * 4 + i) * FPS + c];
            #pragma unroll
            for (int jj = 0; jj < 4; jj++) vf[jj] = Vs[c * FPQ + tx * 4 + jj];
            #pragma unroll
            for (int i = 0; i < 4; i++)
                #pragma unroll
                for (int jj = 0; jj < 4; jj++)
                    acc[i][jj] = fmaf(pf[i], vf[jj], acc[i][jj]);
        }
    }

    // Epilogue: normalize and store to [b, t, h*64+d]
    float linv[4];
    #pragma unroll
    for (int i = 0; i < 4; i++) linv[i] = 1.f / lrow[ty * 4 + i];

    float* op = out + ((size_t)b * SEQ + i0 + ty * 4) * D_MODEL + h * DK + tx * 4;
    #pragma unroll
    for (int i = 0; i < 4; i++) {
        *(float4*)(op + (size_t)i * D_MODEL) =
            make_float4(acc[i][0] * linv[i], acc[i][1] * linv[i],
                        acc[i][2] * linv[i], acc[i][3] * linv[i]);
    }
}

// ----------------------------------------------------------------------------
// kernel_launch: pure kernel launches only — no host runtime APIs at all.
// ----------------------------------------------------------------------------
extern "C" void kernel_launch(void* const* d_in, const int* in_sizes, int n_in,
                              void* d_out, int out_size)
{
    const float* x     = (const float*)d_in[0];
    const float* Wqkv  = (const float*)d_in[1];
    const float* Wproj = (const float*)d_in[2];
    float* out = (float*)d_out;

    const int M = BATCH * SEQ;               // 8192

    // 1) g_qkv = x @ W_qkv   (8192x1024 @ 1024x3072)
    sgemm_kernel<false, true><<<dim3((3 * D_MODEL) / 128, M / 128), 256>>>(
        x, Wqkv, nullptr, M, 3 * D_MODEL, D_MODEL);

    // 2) flash attention: g_qkv -> g_attn
    flash_kernel<<<dim3(SEQ / 64, BATCH * N_HEADS), 256>>>();

    // 3) out = g_attn @ W_proj (8192x1024 @ 1024x1024)
    sgemm_kernel<true, false><<<dim3(D_MODEL / 128, M / 128), 256>>>(
        nullptr, Wproj, out, M, D_MODEL, D_MODEL);
}

// round 4
// speedup vs baseline: 1.5040x; 1.5040x over previous
#include <cuda_runtime.h>
#include <cuda_bf16.h>
#include <cstdint>
#include <cstddef>

#define D_MODEL 1024
#define N_HEADS 16
#define DK      64
#define BATCH   4
#define SEQ     2048
#define FPQ     65
#define MTOT    (BATCH * SEQ)     // 8192

// ---------------- device global scratch (no allocation APIs allowed) --------
__device__ float g_qkv[(size_t)BATCH * SEQ * 3 * D_MODEL];   // 96 MB fp32
__device__ float g_attn[(size_t)BATCH * SEQ * D_MODEL];      // 32 MB fp32
__device__ __nv_bfloat16 g_A_hi[(size_t)MTOT * D_MODEL];
__device__ __nv_bfloat16 g_A_lo[(size_t)MTOT * D_MODEL];
__device__ __nv_bfloat16 g_Wq_hi[(size_t)3 * D_MODEL * D_MODEL]; // [3072][1024] K-major
__device__ __nv_bfloat16 g_Wq_lo[(size_t)3 * D_MODEL * D_MODEL];
__device__ __nv_bfloat16 g_Wp_hi[(size_t)D_MODEL * D_MODEL];     // [1024][1024]
__device__ __nv_bfloat16 g_Wp_lo[(size_t)D_MODEL * D_MODEL];

// ---------------- arch-agnostic PTX helpers (sm_80+ only!) -----------------
__device__ __forceinline__ uint32_t smem_to_u32(const void* p) {
    uint32_t a;
    asm("{ .reg .u64 t; cvta.to.shared.u64 t, %1; cvt.u32.u64 %0, t; }"
        : "=r"(a) : "l"(p));
    return a;
}
__device__ __forceinline__ void cp_async16(uint32_t dst, const void* src) {
    asm volatile("cp.async.cg.shared.global [%0], [%1], 16;\n" :: "r"(dst), "l"(src));
}
__device__ __forceinline__ void cp_commit() {
    asm volatile("cp.async.commit_group;\n" ::: "memory");
}
template <int N>
__device__ __forceinline__ void cp_wait() {
    asm volatile("cp.async.wait_group %0;\n" :: "n"(N) : "memory");
}
__device__ __forceinline__ void mma_bf16(float* d, const uint32_t* a, const uint32_t* b) {
    asm volatile(
        "mma.sync.aligned.m16n8k16.row.col.f32.bf16.bf16.f32 "
        "{%0,%1,%2,%3}, {%4,%5,%6,%7}, {%8,%9}, {%0,%1,%2,%3};\n"
        : "+f"(d[0]), "+f"(d[1]), "+f"(d[2]), "+f"(d[3])
        : "r"(a[0]), "r"(a[1]), "r"(a[2]), "r"(a[3]), "r"(b[0]), "r"(b[1]));
}

// ---------------------------------------------------------------------------
// Prepass 1: split fp32 activations into bf16 hi/lo.
// ---------------------------------------------------------------------------
template <bool FROM_X>
__global__ __launch_bounds__(256) void aprep_kernel(const float* __restrict__ xin)
{
    const float* src = FROM_X ? xin : (const float*)g_attn;
    size_t i = ((size_t)blockIdx.x * 256 + threadIdx.x) * 4;
    float4 v = *(const float4*)(src + i);
    __nv_bfloat16 h0 = __float2bfloat16(v.x), h1 = __float2bfloat16(v.y);
    __nv_bfloat16 h2 = __float2bfloat16(v.z), h3 = __float2bfloat16(v.w);
    __nv_bfloat16 l0 = __float2bfloat16(v.x - __bfloat162float(h0));
    __nv_bfloat16 l1 = __float2bfloat16(v.y - __bfloat162float(h1));
    __nv_bfloat16 l2 = __float2bfloat16(v.z - __bfloat162float(h2));
    __nv_bfloat16 l3 = __float2bfloat16(v.w - __bfloat162float(h3));
    __nv_bfloat162 hp0 = __nv_bfloat162(h0, h1), hp1 = __nv_bfloat162(h2, h3);
    __nv_bfloat162 lp0 = __nv_bfloat162(l0, l1), lp1 = __nv_bfloat162(l2, l3);
    *(uint2*)(g_A_hi + i) = make_uint2(*(uint32_t*)&hp0, *(uint32_t*)&hp1);
    *(uint2*)(g_A_lo + i) = make_uint2(*(uint32_t*)&lp0, *(uint32_t*)&lp1);
}

// ---------------------------------------------------------------------------
// Prepass 2: transpose W [1024][N] -> Wt [N][1024] and split hi/lo bf16.
// ---------------------------------------------------------------------------
template <int WHICH>
__global__ __launch_bounds__(256) void wprep_kernel(const float* __restrict__ W, int N)
{
    __shared__ float t[32][33];
    const int n0 = blockIdx.x * 32, k0 = blockIdx.y * 32;
    const int tx = threadIdx.x, ty = threadIdx.y;
    #pragma unroll
    for (int i = 0; i < 4; i++)
        t[ty + 8 * i][tx] = W[(size_t)(k0 + ty + 8 * i) * N + n0 + tx];
    __syncthreads();
    __nv_bfloat16* hi = (WHICH == 0) ? g_Wq_hi : g_Wp_hi;
    __nv_bfloat16* lo = (WHICH == 0) ? g_Wq_lo : g_Wp_lo;
    #pragma unroll
    for (int i = 0; i < 4; i++) {
        int n = n0 + ty + 8 * i, k = k0 + tx;
        float v = t[tx][ty + 8 * i];
        __nv_bfloat16 h = __float2bfloat16(v);
        hi[(size_t)n * D_MODEL + k] = h;
        lo[(size_t)n * D_MODEL + k] = __float2bfloat16(v - __bfloat162float(h));
    }
}

// ---------------------------------------------------------------------------
// bf16x3 GEMM via mma.sync.m16n8k16 (sm_80+ path — works on base sm_100).
// C[M,N] = A[M,1024] @ W[1024,N].  A hi/lo: [M][1024]; W hi/lo: [N][1024].
// CTA tile 128x128, 8 warps (4x2), warp tile 32x64 (2x8 atoms).
// BK=32, cp.async double buffer. Smem pitch 40 bf16 (80B) -> conflict-free lds.
// Buffer layout (per 40960B buffer): Ah | Al | Bh | Bl, each 128*80 = 10240B.
// ---------------------------------------------------------------------------
#define GPITCH 80          // bytes per smem row (40 bf16)
#define TSZ    10240       // one tensor tile (128 rows * 80B)
#define BUFSZ  40960       // 4 tensors

template <bool IS_QKV>
__global__ __launch_bounds__(256, 1) void mma_gemm(float* __restrict__ Cparam)
{
    extern __shared__ char smem[];
    const int N = IS_QKV ? 3 * D_MODEL : D_MODEL;
    const __nv_bfloat16* BhiG = IS_QKV ? g_Wq_hi : g_Wp_hi;
    const __nv_bfloat16* BloG = IS_QKV ? g_Wq_lo : g_Wp_lo;
    float* C = IS_QKV ? (float*)g_qkv : Cparam;

    const int tid = threadIdx.x;
    const int wid = tid >> 5, lane = tid & 31;
    const int wm = wid & 3, wn = wid >> 2;          // 4 x 2 warp grid
    const int g = lane >> 2, q = lane & 3;
    const int m0 = blockIdx.y * 128, n0 = blockIdx.x * 128;

    const char* srcs[4] = {
        (const char*)(g_A_hi + (size_t)m0 * D_MODEL),
        (const char*)(g_A_lo + (size_t)m0 * D_MODEL),
        (const char*)(BhiG + (size_t)n0 * D_MODEL),
        (const char*)(BloG + (size_t)n0 * D_MODEL) };

    const uint32_t sb = smem_to_u32(smem);

    float acc[2][8][4] = {};

    // issue cp.async loads for K-chunk c into buffer c&1 (2048 x 16B chunks)
    auto issue = [&](int c) {
        const uint32_t buf = sb + (c & 1) * BUFSZ;
        const size_t koff = (size_t)c * 64;        // 32 bf16 = 64 bytes
        #pragma unroll
        for (int i = 0; i < 8; i++) {
            int id = tid + i * 256;                // 0..2047
            int t = id >> 9;                       // tensor 0..3
            int rem = id & 511;
            int row = rem >> 2, c16 = rem & 3;     // 4 x 16B per 64B row
            cp_async16(buf + t * TSZ + row * GPITCH + c16 * 16,
                       srcs[t] + (size_t)row * 2048 + koff + c16 * 16);
        }
        cp_commit();
    };

    issue(0);
    #pragma unroll 1
    for (int c = 0; c < 32; c++) {
        if (c + 1 < 32) { issue(c + 1); cp_wait<1>(); }
        else            { cp_wait<0>(); }
        __syncthreads();

        const char* buf = smem + (c & 1) * BUFSZ;
        #pragma unroll
        for (int ks = 0; ks < 2; ks++) {
            const int kb = ks * 32 + q * 4;        // byte offset of k16 step + quad
            uint32_t ah[2][4], al[2][4], bh[8][2], bl[8][2];
            #pragma unroll
            for (int am = 0; am < 2; am++) {
                const int r0 = wm * 32 + am * 16 + g;
                const char* p0 = buf + (size_t)r0 * GPITCH + kb;
                const char* p1 = buf + (size_t)(r0 + 8) * GPITCH + kb;
                ah[am][0] = *(const uint32_t*)(p0);
                ah[am][1] = *(const uint32_t*)(p1);
                ah[am][2] = *(const uint32_t*)(p0 + 16);
                ah[am][3] = *(const uint32_t*)(p1 + 16);
                al[am][0] = *(const uint32_t*)(p0 + TSZ);
                al[am][1] = *(const uint32_t*)(p1 + TSZ);
                al[am][2] = *(const uint32_t*)(p0 + TSZ + 16);
                al[am][3] = *(const uint32_t*)(p1 + TSZ + 16);
            }
            #pragma unroll
            for (int an = 0; an < 8; an++) {
                const int nr = wn * 64 + an * 8 + g;
                const char* pb = buf + 2 * TSZ + (size_t)nr * GPITCH + kb;
                bh[an][0] = *(const uint32_t*)(pb);
                bh[an][1] = *(const uint32_t*)(pb + 16);
                bl[an][0] = *(const uint32_t*)(pb + TSZ);
                bl[an][1] = *(const uint32_t*)(pb + TSZ + 16);
            }
            #pragma unroll
            for (int am = 0; am < 2; am++)
                #pragma unroll
                for (int an = 0; an < 8; an++) {
                    mma_bf16(acc[am][an], ah[am], bh[an]);   // hh
                    mma_bf16(acc[am][an], ah[am], bl[an]);   // hl
                    mma_bf16(acc[am][an], al[am], bh[an]);   // lh
                }
        }
        __syncthreads();
    }

    // epilogue
    #pragma unroll
    for (int am = 0; am < 2; am++) {
        const int row = m0 + wm * 32 + am * 16 + g;
        #pragma unroll
        for (int an = 0; an < 8; an++) {
            const int col = n0 + wn * 64 + an * 8 + q * 2;
            *(float2*)(C + (size_t)row * N + col) =
                make_float2(acc[am][an][0], acc[am][an][1]);
            *(float2*)(C + (size_t)(row + 8) * N + col) =
                make_float2(acc[am][an][2], acc[am][an][3]);
        }
    }
}

// ---------------------------------------------------------------------------
// Flash attention (causal), fp32, 64-query x 64-key tiles (dynamic smem).
// ---------------------------------------------------------------------------
__global__ __launch_bounds__(256) void flash_kernel()
{
    extern __shared__ float sm[];
    float* Qs   = sm;                 // 64*FPQ
    float* Ks   = Qs + 64 * FPQ;
    float* Vs   = Ks + 64 * FPQ;
    float* Ss   = Vs + 64 * FPQ;
    float* mrow = Ss + 64 * FPQ;      // 64
    float* lrow = mrow + 64;
    float* arow = lrow + 64;

    const float* qkv = (const float*)g_qkv;
    float*       out = (float*)g_attn;

    const int tid = threadIdx.x;
    const int ty = tid >> 4, tx = tid & 15;
    const int bh = blockIdx.y;
    const int b = bh >> 4, h = bh & 15;
    const int i0 = blockIdx.x * 64;

    const float* base = qkv + (size_t)b * SEQ * 3 * D_MODEL + h * DK;

    #pragma unroll
    for (int v = 0; v < 4; v++) {
        int e = v * 1024 + tid * 4;
        int r = e >> 6, c = e & 63;
        float4 q4 = *(const float4*)(base + (size_t)(i0 + r) * (3 * D_MODEL) + c);
        float* dst = Qs + r * FPQ + c;
        dst[0] = q4.x * 0.125f; dst[1] = q4.y * 0.125f;
        dst[2] = q4.z * 0.125f; dst[3] = q4.w * 0.125f;
    }
    if (tid < 64) { mrow[tid] = -1e30f; lrow[tid] = 0.f; }

    float acc[4][4];
    #pragma unroll
    for (int i = 0; i < 4; i++)
        #pragma unroll
        for (int j = 0; j < 4; j++) acc[i][j] = 0.f;

    const int jmax = blockIdx.x;
    for (int j = 0; j <= jmax; j++) {
        const int j0 = j * 64;
        __syncthreads();

        #pragma unroll
        for (int v = 0; v < 4; v++) {
            int e = v * 1024 + tid * 4;
            int r = e >> 6, c = e & 63;
            const float* kp = base + (size_t)(j0 + r) * (3 * D_MODEL) + D_MODEL + c;
            float4 k4 = *(const float4*)kp;
            float4 v4 = *(const float4*)(kp + D_MODEL);
            float* kd = Ks + r * FPQ + c;
            kd[0] = k4.x; kd[1] = k4.y; kd[2] = k4.z; kd[3] = k4.w;
            float* vd = Vs + r * FPQ + c;
            vd[0] = v4.x; vd[1] = v4.y; vd[2] = v4.z; vd[3] = v4.w;
        }
        __syncthreads();

        float sacc[4][4];
        #pragma unroll
        for (int i = 0; i < 4; i++)
            #pragma unroll
            for (int jj = 0; jj < 4; jj++) sacc[i][jj] = 0.f;

        #pragma unroll 8
        for (int k = 0; k < 64; k++) {
            float qf[4], kf[4];
            #pragma unroll
            for (int i = 0; i < 4; i++)  qf[i]  = Qs[(ty * 4 + i) * FPQ + k];
            #pragma unroll
            for (int jj = 0; jj < 4; jj++) kf[jj] = Ks[(tx * 4 + jj) * FPQ + k];
            #pragma unroll
            for (int i = 0; i < 4; i++)
                #pragma unroll
                for (int jj = 0; jj < 4; jj++)
                    sacc[i][jj] = fmaf(qf[i], kf[jj], sacc[i][jj]);
        }

        const bool diag = (j == jmax);
        #pragma unroll
        for (int i = 0; i < 4; i++) {
            int r = ty * 4 + i;
            #pragma unroll
            for (int jj = 0; jj < 4; jj++) {
                int c = tx * 4 + jj;
                float s = sacc[i][jj];
                if (diag && c > r) s = -1e9f;
                Ss[r * FPQ + c] = s;
            }
        }
        __syncthreads();

        if (tid < 64) {
            int r = tid;
            float mold = mrow[r];
            float mx = mold;
            #pragma unroll 8
            for (int c = 0; c < 64; c++) mx = fmaxf(mx, Ss[r * FPQ + c]);
            float a = __expf(mold - mx);
            float sum = 0.f;
            #pragma unroll 8
            for (int c = 0; c < 64; c++) {
                float p = __expf(Ss[r * FPQ + c] - mx);
                Ss[r * FPQ + c] = p;
                sum += p;
            }
            lrow[r] = lrow[r] * a + sum;
            mrow[r] = mx;
            arow[r] = a;
        }
        __syncthreads();

        float al[4];
        #pragma unroll
        for (int i = 0; i < 4; i++) al[i] = arow[ty * 4 + i];
        #pragma unroll
        for (int i = 0; i < 4; i++)
            #pragma unroll
            for (int jj = 0; jj < 4; jj++) acc[i][jj] *= al[i];

        #pragma unroll 8
        for (int c = 0; c < 64; c++) {
            float pf[4], vf[4];
            #pragma unroll
            for (int i = 0; i < 4; i++)  pf[i]  = Ss[(ty * 4 + i) * FPQ + c];
            #pragma unroll
            for (int jj = 0; jj < 4; jj++) vf[jj] = Vs[c * FPQ + tx * 4 + jj];
            #pragma unroll
            for (int i = 0; i < 4; i++)
                #pragma unroll
                for (int jj = 0; jj < 4; jj++)
                    acc[i][jj] = fmaf(pf[i], vf[jj], acc[i][jj]);
        }
    }

    float linv[4];
    #pragma unroll
    for (int i = 0; i < 4; i++) linv[i] = 1.f / lrow[ty * 4 + i];

    float* op = out + ((size_t)b * SEQ + i0 + ty * 4) * D_MODEL + h * DK + tx * 4;
    #pragma unroll
    for (int i = 0; i < 4; i++) {
        *(float4*)(op + (size_t)i * D_MODEL) =
            make_float4(acc[i][0] * linv[i], acc[i][1] * linv[i],
                        acc[i][2] * linv[i], acc[i][3] * linv[i]);
    }
}

// ---------------------------------------------------------------------------
extern "C" void kernel_launch(void* const* d_in, const int* in_sizes, int n_in,
                              void* d_out, int out_size)
{
    const float* x     = (const float*)d_in[0];
    const float* Wqkv  = (const float*)d_in[1];
    const float* Wproj = (const float*)d_in[2];
    float* out = (float*)d_out;

    const int GEMM_SMEM  = 2 * BUFSZ;                                  // 80 KB
    const int FLASH_SMEM = (4 * 64 * FPQ + 3 * 64) * (int)sizeof(float); // ~67 KB
    cudaFuncSetAttribute(mma_gemm<true>,
                         cudaFuncAttributeMaxDynamicSharedMemorySize, GEMM_SMEM);
    cudaFuncSetAttribute(mma_gemm<false>,
                         cudaFuncAttributeMaxDynamicSharedMemorySize, GEMM_SMEM);
    cudaFuncSetAttribute(flash_kernel,
                         cudaFuncAttributeMaxDynamicSharedMemorySize, FLASH_SMEM);

    // weight prepasses
    wprep_kernel<0><<<dim3(3 * D_MODEL / 32, D_MODEL / 32), dim3(32, 8)>>>(Wqkv, 3 * D_MODEL);
    wprep_kernel<1><<<dim3(D_MODEL / 32, D_MODEL / 32), dim3(32, 8)>>>(Wproj, D_MODEL);

    // x -> hi/lo
    aprep_kernel<true><<<(size_t)MTOT * D_MODEL / 4 / 256, 256>>>(x);

    // qkv = x @ W_qkv
    mma_gemm<true><<<dim3(3 * D_MODEL / 128, MTOT / 128), 256, GEMM_SMEM>>>(nullptr);

    // flash attention
    flash_kernel<<<dim3(SEQ / 64, BATCH * N_HEADS), 256, FLASH_SMEM>>>();

    // attn -> hi/lo
    aprep_kernel<false><<<(size_t)MTOT * D_MODEL / 4 / 256, 256>>>(nullptr);

    // out = attn @ W_proj
    mma_gemm<false><<<dim3(D_MODEL / 128, MTOT / 128), 256, GEMM_SMEM>>>(out);
}

// round 5
// speedup vs baseline: 2.6543x; 1.7649x over previous
#include <cuda_runtime.h>
#include <cuda_bf16.h>
#include <cstdint>
#include <cstddef>

#define D_MODEL 1024
#define N_HEADS 16
#define DK      64
#define BATCH   4
#define SEQ     2048
#define MTOT    (BATCH * SEQ)     // 8192
#define BH      (BATCH * N_HEADS) // 64

// ---------------- device global scratch (no allocation APIs allowed) --------
__device__ float g_qkv[(size_t)MTOT * 3 * D_MODEL];              // 96 MB fp32
__device__ __nv_bfloat16 g_A_hi[(size_t)MTOT * D_MODEL];         // GEMM A input (x, then attn)
__device__ __nv_bfloat16 g_A_lo[(size_t)MTOT * D_MODEL];
__device__ __nv_bfloat16 g_Wq_hi[(size_t)3 * D_MODEL * D_MODEL]; // [3072][1024] K-major
__device__ __nv_bfloat16 g_Wq_lo[(size_t)3 * D_MODEL * D_MODEL];
__device__ __nv_bfloat16 g_Wp_hi[(size_t)D_MODEL * D_MODEL];
__device__ __nv_bfloat16 g_Wp_lo[(size_t)D_MODEL * D_MODEL];
// flash operands, per (b,h) planar
__device__ __nv_bfloat16 g_Qh[(size_t)BH * SEQ * DK];            // [bh][t][64], pre-scaled
__device__ __nv_bfloat16 g_Ql[(size_t)BH * SEQ * DK];
__device__ __nv_bfloat16 g_Kh[(size_t)BH * SEQ * DK];
__device__ __nv_bfloat16 g_Kl[(size_t)BH * SEQ * DK];
__device__ __nv_bfloat16 g_Vth[(size_t)BH * DK * SEQ];           // [bh][d][t]  (V transposed)
__device__ __nv_bfloat16 g_Vtl[(size_t)BH * DK * SEQ];

// ---------------- arch-agnostic PTX helpers (sm_80+ only) ------------------
__device__ __forceinline__ uint32_t smem_to_u32(const void* p) {
    uint32_t a;
    asm("{ .reg .u64 t; cvta.to.shared.u64 t, %1; cvt.u32.u64 %0, t; }"
        : "=r"(a) : "l"(p));
    return a;
}
__device__ __forceinline__ void cp_async16(uint32_t dst, const void* src) {
    asm volatile("cp.async.cg.shared.global [%0], [%1], 16;\n" :: "r"(dst), "l"(src));
}
__device__ __forceinline__ void cp_commit() {
    asm volatile("cp.async.commit_group;\n" ::: "memory");
}
template <int N>
__device__ __forceinline__ void cp_wait() {
    asm volatile("cp.async.wait_group %0;\n" :: "n"(N) : "memory");
}
__device__ __forceinline__ void mma_bf16(float* d, const uint32_t* a, const uint32_t* b) {
    asm volatile(
        "mma.sync.aligned.m16n8k16.row.col.f32.bf16.bf16.f32 "
        "{%0,%1,%2,%3}, {%4,%5,%6,%7}, {%8,%9}, {%0,%1,%2,%3};\n"
        : "+f"(d[0]), "+f"(d[1]), "+f"(d[2]), "+f"(d[3])
        : "r"(a[0]), "r"(a[1]), "r"(a[2]), "r"(a[3]), "r"(b[0]), "r"(b[1]));
}
// split two fp32 into packed bf16x2 hi and lo-residual
__device__ __forceinline__ void split2(float x, float y, uint32_t& hi, uint32_t& lo) {
    __nv_bfloat16 hx = __float2bfloat16(x), hy = __float2bfloat16(y);
    __nv_bfloat16 lx = __float2bfloat16(x - __bfloat162float(hx));
    __nv_bfloat16 ly = __float2bfloat16(y - __bfloat162float(hy));
    __nv_bfloat162 hp(hx, hy), lp(lx, ly);
    hi = *(uint32_t*)&hp; lo = *(uint32_t*)&lp;
}

// ---------------------------------------------------------------------------
// Prepass: split fp32 x into bf16 hi/lo (GEMM A input).
// ---------------------------------------------------------------------------
__global__ __launch_bounds__(256) void aprep_kernel(const float* __restrict__ xin)
{
    size_t i = ((size_t)blockIdx.x * 256 + threadIdx.x) * 4;
    float4 v = *(const float4*)(xin + i);
    uint32_t h0, l0, h1, l1;
    split2(v.x, v.y, h0, l0);
    split2(v.z, v.w, h1, l1);
    *(uint2*)(g_A_hi + i) = make_uint2(h0, h1);
    *(uint2*)(g_A_lo + i) = make_uint2(l0, l1);
}

// ---------------------------------------------------------------------------
// Prepass: transpose W [1024][N] -> [N][1024] and split hi/lo.
// ---------------------------------------------------------------------------
template <int WHICH>
__global__ __launch_bounds__(256) void wprep_kernel(const float* __restrict__ W, int N)
{
    __shared__ float t[32][33];
    const int n0 = blockIdx.x * 32, k0 = blockIdx.y * 32;
    const int tx = threadIdx.x, ty = threadIdx.y;
    #pragma unroll
    for (int i = 0; i < 4; i++)
        t[ty + 8 * i][tx] = W[(size_t)(k0 + ty + 8 * i) * N + n0 + tx];
    __syncthreads();
    __nv_bfloat16* hi = (WHICH == 0) ? g_Wq_hi : g_Wp_hi;
    __nv_bfloat16* lo = (WHICH == 0) ? g_Wq_lo : g_Wp_lo;
    #pragma unroll
    for (int i = 0; i < 4; i++) {
        int n = n0 + ty + 8 * i, k = k0 + tx;
        float v = t[tx][ty + 8 * i];
        __nv_bfloat16 h = __float2bfloat16(v);
        hi[(size_t)n * D_MODEL + k] = h;
        lo[(size_t)n * D_MODEL + k] = __float2bfloat16(v - __bfloat162float(h));
    }
}

// ---------------------------------------------------------------------------
// bf16x3 GEMM via mma.sync.m16n8k16 (unchanged from passing round-4 kernel).
// ---------------------------------------------------------------------------
#define GPITCH 80
#define TSZ    10240
#define BUFSZ  40960

template <bool IS_QKV>
__global__ __launch_bounds__(256, 1) void mma_gemm(float* __restrict__ Cparam)
{
    extern __shared__ char smem[];
    const int N = IS_QKV ? 3 * D_MODEL : D_MODEL;
    const __nv_bfloat16* BhiG = IS_QKV ? g_Wq_hi : g_Wp_hi;
    const __nv_bfloat16* BloG = IS_QKV ? g_Wq_lo : g_Wp_lo;
    float* C = IS_QKV ? (float*)g_qkv : Cparam;

    const int tid = threadIdx.x;
    const int wid = tid >> 5, lane = tid & 31;
    const int wm = wid & 3, wn = wid >> 2;
    const int g = lane >> 2, q = lane & 3;
    const int m0 = blockIdx.y * 128, n0 = blockIdx.x * 128;

    const char* srcs[4] = {
        (const char*)(g_A_hi + (size_t)m0 * D_MODEL),
        (const char*)(g_A_lo + (size_t)m0 * D_MODEL),
        (const char*)(BhiG + (size_t)n0 * D_MODEL),
        (const char*)(BloG + (size_t)n0 * D_MODEL) };

    const uint32_t sb = smem_to_u32(smem);
    float acc[2][8][4] = {};

    auto issue = [&](int c) {
        const uint32_t buf = sb + (c & 1) * BUFSZ;
        const size_t koff = (size_t)c * 64;
        #pragma unroll
        for (int i = 0; i < 8; i++) {
            int id = tid + i * 256;
            int t = id >> 9;
            int rem = id & 511;
            int row = rem >> 2, c16 = rem & 3;
            cp_async16(buf + t * TSZ + row * GPITCH + c16 * 16,
                       srcs[t] + (size_t)row * 2048 + koff + c16 * 16);
        }
        cp_commit();
    };

    issue(0);
    #pragma unroll 1
    for (int c = 0; c < 32; c++) {
        if (c + 1 < 32) { issue(c + 1); cp_wait<1>(); }
        else            { cp_wait<0>(); }
        __syncthreads();

        const char* buf = smem + (c & 1) * BUFSZ;
        #pragma unroll
        for (int ks = 0; ks < 2; ks++) {
            const int kb = ks * 32 + q * 4;
            uint32_t ah[2][4], al[2][4], bh[8][2], bl[8][2];
            #pragma unroll
            for (int am = 0; am < 2; am++) {
                const int r0 = wm * 32 + am * 16 + g;
                const char* p0 = buf + (size_t)r0 * GPITCH + kb;
                const char* p1 = buf + (size_t)(r0 + 8) * GPITCH + kb;
                ah[am][0] = *(const uint32_t*)(p0);
                ah[am][1] = *(const uint32_t*)(p1);
                ah[am][2] = *(const uint32_t*)(p0 + 16);
                ah[am][3] = *(const uint32_t*)(p1 + 16);
                al[am][0] = *(const uint32_t*)(p0 + TSZ);
                al[am][1] = *(const uint32_t*)(p1 + TSZ);
                al[am][2] = *(const uint32_t*)(p0 + TSZ + 16);
                al[am][3] = *(const uint32_t*)(p1 + TSZ + 16);
            }
            #pragma unroll
            for (int an = 0; an < 8; an++) {
                const int nr = wn * 64 + an * 8 + g;
                const char* pb = buf + 2 * TSZ + (size_t)nr * GPITCH + kb;
                bh[an][0] = *(const uint32_t*)(pb);
                bh[an][1] = *(const uint32_t*)(pb + 16);
                bl[an][0] = *(const uint32_t*)(pb + TSZ);
                bl[an][1] = *(const uint32_t*)(pb + TSZ + 16);
            }
            #pragma unroll
            for (int am = 0; am < 2; am++)
                #pragma unroll
                for (int an = 0; an < 8; an++) {
                    mma_bf16(acc[am][an], ah[am], bh[an]);
                    mma_bf16(acc[am][an], ah[am], bl[an]);
                    mma_bf16(acc[am][an], al[am], bh[an]);
                }
        }
        __syncthreads();
    }

    #pragma unroll
    for (int am = 0; am < 2; am++) {
        const int row = m0 + wm * 32 + am * 16 + g;
        #pragma unroll
        for (int an = 0; an < 8; an++) {
            const int col = n0 + wn * 64 + an * 8 + q * 2;
            *(float2*)(C + (size_t)row * N + col) =
                make_float2(acc[am][an][0], acc[am][an][1]);
            *(float2*)(C + (size_t)(row + 8) * N + col) =
                make_float2(acc[am][an][2], acc[am][an][3]);
        }
    }
}

// ---------------------------------------------------------------------------
// qkv_split: g_qkv fp32 -> planar bf16 hi/lo Q (x0.125), K, and V transposed.
// Block = (64 t) x (one bh). 256 threads.
// ---------------------------------------------------------------------------
__global__ __launch_bounds__(256) void qkv_split_kernel()
{
    __shared__ float vtile[64][65];
    const int bh = blockIdx.y;
    const int b = bh >> 4, h = bh & 15;
    const int i0 = blockIdx.x * 64;
    const int tid = threadIdx.x;

    const float* src = g_qkv + ((size_t)b * SEQ + i0) * (3 * D_MODEL) + h * DK;

    #pragma unroll
    for (int it = 0; it < 16; it++) {
        int idx = tid + it * 256;          // 0..4095
        int t = idx >> 6, d = idx & 63;
        const float* p = src + (size_t)t * (3 * D_MODEL) + d;
        float qv = p[0] * 0.125f;
        float kv = p[D_MODEL];
        float vv = p[2 * D_MODEL];
        size_t o = ((size_t)bh * SEQ + i0 + t) * DK + d;
        __nv_bfloat16 qh = __float2bfloat16(qv);
        g_Qh[o] = qh;
        g_Ql[o] = __float2bfloat16(qv - __bfloat162float(qh));
        __nv_bfloat16 kh = __float2bfloat16(kv);
        g_Kh[o] = kh;
        g_Kl[o] = __float2bfloat16(kv - __bfloat162float(kh));
        vtile[t][d] = vv;
    }
    __syncthreads();
    #pragma unroll
    for (int it = 0; it < 16; it++) {
        int idx = tid + it * 256;
        int d = idx >> 6, t = idx & 63;
        float vv = vtile[t][d];
        size_t o = ((size_t)bh * DK + d) * SEQ + i0 + t;
        __nv_bfloat16 vh = __float2bfloat16(vv);
        g_Vth[o] = vh;
        g_Vtl[o] = __float2bfloat16(vv - __bfloat162float(vh));
    }
}

// ---------------------------------------------------------------------------
// flash_mma: FA2-style bf16x3 attention on mma.sync.
// 128 threads (4 warps), block = 64 queries x one (b,h). Key tiles of 64.
// Writes output directly as bf16 hi/lo into g_A_hi/g_A_lo ([t][1024] layout).
// ---------------------------------------------------------------------------
#define KP 144   // smem pitch bytes for 64 bf16 rows (72 bf16): banks 4g+q, conflict-free

__global__ __launch_bounds__(128) void flash_mma()
{
    __shared__ __align__(16) char sKh[64 * KP];
    __shared__ __align__(16) char sKl[64 * KP];
    __shared__ __align__(16) char sVh[64 * KP];   // V^T tile: rows d, cols j
    __shared__ __align__(16) char sVl[64 * KP];

    const int tid = threadIdx.x;
    const int w = tid >> 5, lane = tid & 31;
    const int g = lane >> 2, q = lane & 3;
    const int bh = blockIdx.y;
    const int b = bh >> 4, h = bh & 15;
    const int i0 = blockIdx.x * 64;
    const int rloc = 16 * w + g;               // local query row (c0,c1); +8 for c2,c3

    // Q fragments (resident, loaded once)
    uint32_t qh[4][4], ql[4][4];
    {
        const size_t base = ((size_t)bh * SEQ + i0 + rloc) * DK;
        #pragma unroll
        for (int ks = 0; ks < 4; ks++) {
            size_t e = base + ks * 16 + 2 * q;
            qh[ks][0] = *(const uint32_t*)(g_Qh + e);
            qh[ks][1] = *(const uint32_t*)(g_Qh + e + 8 * DK);
            qh[ks][2] = *(const uint32_t*)(g_Qh + e + 8);
            qh[ks][3] = *(const uint32_t*)(g_Qh + e + 8 * DK + 8);
            ql[ks][0] = *(const uint32_t*)(g_Ql + e);
            ql[ks][1] = *(const uint32_t*)(g_Ql + e + 8 * DK);
            ql[ks][2] = *(const uint32_t*)(g_Ql + e + 8);
            ql[ks][3] = *(const uint32_t*)(g_Ql + e + 8 * DK + 8);
        }
    }

    float o[8][4] = {};
    float m0 = -1e30f, m1 = -1e30f, l0 = 0.f, l1 = 0.f;

    const int jmax = blockIdx.x;
    #pragma unroll 1
    for (int jt = 0; jt <= jmax; jt++) {
        const int j0 = jt * 64;
        __syncthreads();
        // load K/V tiles: 4 arrays x 512 uint4, 16 uint4/thread
        {
            const __nv_bfloat16* gsrc[4] = {
                g_Kh  + ((size_t)bh * SEQ + j0) * DK,
                g_Kl  + ((size_t)bh * SEQ + j0) * DK,
                g_Vth + ((size_t)bh * DK) * SEQ + j0,
                g_Vtl + ((size_t)bh * DK) * SEQ + j0 };
            char* dsts[4] = { sKh, sKl, sVh, sVl };
            #pragma unroll
            for (int a = 0; a < 4; a++) {
                const size_t rstride = (a < 2) ? DK : SEQ;   // row stride in elems
                #pragma unroll
                for (int i = 0; i < 4; i++) {
                    int id = tid + i * 128;                  // 0..511
                    int row = id >> 3, c8 = id & 7;
                    uint4 v = *(const uint4*)(gsrc[a] + (size_t)row * rstride + c8 * 8);
                    *(uint4*)(dsts[a] + row * KP + c8 * 16) = v;
                }
            }
        }
        __syncthreads();

        // S = Qh*Kh + Qh*Kl + Ql*Kh
        float s[8][4];
        #pragma unroll
        for (int an = 0; an < 8; an++) {
            s[an][0] = s[an][1] = s[an][2] = s[an][3] = 0.f;
            #pragma unroll
            for (int ks = 0; ks < 4; ks++) {
                const char* pK = sKh + (an * 8 + g) * KP + ks * 32 + q * 4;
                uint32_t b2h[2] = { *(const uint32_t*)pK, *(const uint32_t*)(pK + 16) };
                const char* pKl = sKl + (an * 8 + g) * KP + ks * 32 + q * 4;
                uint32_t b2l[2] = { *(const uint32_t*)pKl, *(const uint32_t*)(pKl + 16) };
                mma_bf16(s[an], qh[ks], b2h);
                mma_bf16(s[an], qh[ks], b2l);
                mma_bf16(s[an], ql[ks], b2h);
            }
        }

        // causal mask on diagonal tile
        if (jt == jmax) {
            #pragma unroll
            for (int an = 0; an < 8; an++) {
                int c0 = an * 8 + 2 * q, c1 = c0 + 1;
                if (c0 > rloc)     s[an][0] = -1e9f;
                if (c1 > rloc)     s[an][1] = -1e9f;
                if (c0 > rloc + 8) s[an][2] = -1e9f;
                if (c1 > rloc + 8) s[an][3] = -1e9f;
            }
        }

        // online softmax (rows rloc and rloc+8; quad = lanes sharing g)
        float mx0 = -1e30f, mx1 = -1e30f;
        #pragma unroll
        for (int an = 0; an < 8; an++) {
            mx0 = fmaxf(mx0, fmaxf(s[an][0], s[an][1]));
            mx1 = fmaxf(mx1, fmaxf(s[an][2], s[an][3]));
        }
        mx0 = fmaxf(mx0, __shfl_xor_sync(0xFFFFFFFF, mx0, 1));
        mx0 = fmaxf(mx0, __shfl_xor_sync(0xFFFFFFFF, mx0, 2));
        mx1 = fmaxf(mx1, __shfl_xor_sync(0xFFFFFFFF, mx1, 1));
        mx1 = fmaxf(mx1, __shfl_xor_sync(0xFFFFFFFF, mx1, 2));
        float mn0 = fmaxf(m0, mx0), mn1 = fmaxf(m1, mx1);
        float a0 = __expf(m0 - mn0), a1 = __expf(m1 - mn1);
        float sum0 = 0.f, sum1 = 0.f;
        #pragma unroll
        for (int an = 0; an < 8; an++) {
            s[an][0] = __expf(s[an][0] - mn0);
            s[an][1] = __expf(s[an][1] - mn0);
            s[an][2] = __expf(s[an][2] - mn1);
            s[an][3] = __expf(s[an][3] - mn1);
            sum0 += s[an][0] + s[an][1];
            sum1 += s[an][2] + s[an][3];
        }
        sum0 += __shfl_xor_sync(0xFFFFFFFF, sum0, 1);
        sum0 += __shfl_xor_sync(0xFFFFFFFF, sum0, 2);
        sum1 += __shfl_xor_sync(0xFFFFFFFF, sum1, 1);
        sum1 += __shfl_xor_sync(0xFFFFFFFF, sum1, 2);
        l0 = l0 * a0 + sum0;  l1 = l1 * a1 + sum1;
        m0 = mn0;  m1 = mn1;
        #pragma unroll
        for (int an = 0; an < 8; an++) {
            o[an][0] *= a0; o[an][1] *= a0;
            o[an][2] *= a1; o[an][3] *= a1;
        }

        // P -> bf16 hi/lo A-fragments (register-local repack)
        uint32_t ph[4][4], pl[4][4];
        #pragma unroll
        for (int kb = 0; kb < 4; kb++) {
            split2(s[2 * kb][0],     s[2 * kb][1],     ph[kb][0], pl[kb][0]);
            split2(s[2 * kb][2],     s[2 * kb][3],     ph[kb][1], pl[kb][1]);
            split2(s[2 * kb + 1][0], s[2 * kb + 1][1], ph[kb][2], pl[kb][2]);
            split2(s[2 * kb + 1][2], s[2 * kb + 1][3], ph[kb][3], pl[kb][3]);
        }

        // O += Ph*Vh + Ph*Vl + Pl*Vh   (B from V^T tile: rows d, cols j)
        #pragma unroll
        for (int an = 0; an < 8; an++) {
            #pragma unroll
            for (int kb = 0; kb < 4; kb++) {
                const char* pV = sVh + (an * 8 + g) * KP + kb * 32 + q * 4;
                uint32_t v2h[2] = { *(const uint32_t*)pV, *(const uint32_t*)(pV + 16) };
                const char* pVl = sVl + (an * 8 + g) * KP + kb * 32 + q * 4;
                uint32_t v2l[2] = { *(const uint32_t*)pVl, *(const uint32_t*)(pVl + 16) };
                mma_bf16(o[an], ph[kb], v2h);
                mma_bf16(o[an], ph[kb], v2l);
                mma_bf16(o[an], pl[kb], v2h);
            }
        }
    }

    // epilogue: normalize, split hi/lo, write proj-GEMM input layout [t][1024]
    const float li0 = 1.f / l0, li1 = 1.f / l1;
    const size_t row0 = (size_t)b * SEQ + i0 + rloc;
    #pragma unroll
    for (int an = 0; an < 8; an++) {
        const int col = h * DK + an * 8 + 2 * q;
        uint32_t hi, lo;
        split2(o[an][0] * li0, o[an][1] * li0, hi, lo);
        *(uint32_t*)(g_A_hi + row0 * D_MODEL + col) = hi;
        *(uint32_t*)(g_A_lo + row0 * D_MODEL + col) = lo;
        split2(o[an][2] * li1, o[an][3] * li1, hi, lo);
        *(uint32_t*)(g_A_hi + (row0 + 8) * D_MODEL + col) = hi;
        *(uint32_t*)(g_A_lo + (row0 + 8) * D_MODEL + col) = lo;
    }
}

// ---------------------------------------------------------------------------
extern "C" void kernel_launch(void* const* d_in, const int* in_sizes, int n_in,
                              void* d_out, int out_size)
{
    const float* x     = (const float*)d_in[0];
    const float* Wqkv  = (const float*)d_in[1];
    const float* Wproj = (const float*)d_in[2];
    float* out = (float*)d_out;

    const int GEMM_SMEM = 2 * BUFSZ;   // 80 KB
    cudaFuncSetAttribute(mma_gemm<true>,
                         cudaFuncAttributeMaxDynamicSharedMemorySize, GEMM_SMEM);
    cudaFuncSetAttribute(mma_gemm<false>,
                         cudaFuncAttributeMaxDynamicSharedMemorySize, GEMM_SMEM);

    // weight prepasses
    wprep_kernel<0><<<dim3(3 * D_MODEL / 32, D_MODEL / 32), dim3(32, 8)>>>(Wqkv, 3 * D_MODEL);
    wprep_kernel<1><<<dim3(D_MODEL / 32, D_MODEL / 32), dim3(32, 8)>>>(Wproj, D_MODEL);

    // x -> hi/lo
    aprep_kernel<<<(size_t)MTOT * D_MODEL / 4 / 256, 256>>>(x);

    // qkv = x @ W_qkv
    mma_gemm<true><<<dim3(3 * D_MODEL / 128, MTOT / 128), 256, GEMM_SMEM>>>(nullptr);

    // split qkv into flash operand layouts
    qkv_split_kernel<<<dim3(SEQ / 64, BH), 256>>>();

    // tensor-core flash attention -> writes g_A_hi/g_A_lo directly
    flash_mma<<<dim3(SEQ / 64, BH), 128>>>();

    // out = attn @ W_proj
    mma_gemm<false><<<dim3(D_MODEL / 128, MTOT / 128), 256, GEMM_SMEM>>>(out);
}

// round 7
// speedup vs baseline: 2.8278x; 1.0654x over previous
#include <cuda_runtime.h>
#include <cuda_bf16.h>
#include <cstdint>
#include <cstddef>

#define D_MODEL 1024
#define N_HEADS 16
#define DK      64
#define BATCH   4
#define SEQ     2048
#define MTOT    (BATCH * SEQ)     // 8192
#define BH      (BATCH * N_HEADS) // 64

// ---------------- device global scratch (no allocation APIs allowed) --------
__device__ float g_qkv[(size_t)MTOT * 3 * D_MODEL];              // 96 MB fp32
__device__ __nv_bfloat16 g_A_hi[(size_t)MTOT * D_MODEL];         // GEMM A input (x, then attn)
__device__ __nv_bfloat16 g_A_lo[(size_t)MTOT * D_MODEL];
__device__ __nv_bfloat16 g_Wq_hi[(size_t)3 * D_MODEL * D_MODEL]; // [3072][1024] K-major
__device__ __nv_bfloat16 g_Wq_lo[(size_t)3 * D_MODEL * D_MODEL];
__device__ __nv_bfloat16 g_Wp_hi[(size_t)D_MODEL * D_MODEL];
__device__ __nv_bfloat16 g_Wp_lo[(size_t)D_MODEL * D_MODEL];
// flash operands, per (b,h) planar
__device__ __nv_bfloat16 g_Qh[(size_t)BH * SEQ * DK];            // [bh][t][64], pre-scaled
__device__ __nv_bfloat16 g_Ql[(size_t)BH * SEQ * DK];
__device__ __nv_bfloat16 g_Kh[(size_t)BH * SEQ * DK];
__device__ __nv_bfloat16 g_Kl[(size_t)BH * SEQ * DK];
__device__ __nv_bfloat16 g_Vth[(size_t)BH * DK * SEQ];           // [bh][d][t]  (V transposed)
__device__ __nv_bfloat16 g_Vtl[(size_t)BH * DK * SEQ];

// ---------------- arch-agnostic PTX helpers (sm_80+ only) ------------------
__device__ __forceinline__ uint32_t smem_to_u32(const void* p) {
    uint32_t a;
    asm("{ .reg .u64 t; cvta.to.shared.u64 t, %1; cvt.u32.u64 %0, t; }"
        : "=r"(a) : "l"(p));
    return a;
}
__device__ __forceinline__ void cp_async16(uint32_t dst, const void* src) {
    asm volatile("cp.async.cg.shared.global [%0], [%1], 16;\n" :: "r"(dst), "l"(src));
}
__device__ __forceinline__ void cp_commit() {
    asm volatile("cp.async.commit_group;\n" ::: "memory");
}
template <int N>
__device__ __forceinline__ void cp_wait() {
    asm volatile("cp.async.wait_group %0;\n" :: "n"(N) : "memory");
}
__device__ __forceinline__ void mma_bf16(float* d, const uint32_t* a, const uint32_t* b) {
    asm volatile(
        "mma.sync.aligned.m16n8k16.row.col.f32.bf16.bf16.f32 "
        "{%0,%1,%2,%3}, {%4,%5,%6,%7}, {%8,%9}, {%0,%1,%2,%3};\n"
        : "+f"(d[0]), "+f"(d[1]), "+f"(d[2]), "+f"(d[3])
        : "r"(a[0]), "r"(a[1]), "r"(a[2]), "r"(a[3]), "r"(b[0]), "r"(b[1]));
}
// split two fp32 into packed bf16x2 hi and lo-residual
__device__ __forceinline__ void split2(float x, float y, uint32_t& hi, uint32_t& lo) {
    __nv_bfloat16 hx = __float2bfloat16(x), hy = __float2bfloat16(y);
    __nv_bfloat16 lx = __float2bfloat16(x - __bfloat162float(hx));
    __nv_bfloat16 ly = __float2bfloat16(y - __bfloat162float(hy));
    __nv_bfloat162 hp(hx, hy), lp(lx, ly);
    hi = *(uint32_t*)&hp; lo = *(uint32_t*)&lp;
}

// ---------------------------------------------------------------------------
// Prepass: split fp32 x into bf16 hi/lo (GEMM A input).
// ---------------------------------------------------------------------------
__global__ __launch_bounds__(256) void aprep_kernel(const float* __restrict__ xin)
{
    size_t i = ((size_t)blockIdx.x * 256 + threadIdx.x) * 4;
    float4 v = *(const float4*)(xin + i);
    uint32_t h0, l0, h1, l1;
    split2(v.x, v.y, h0, l0);
    split2(v.z, v.w, h1, l1);
    *(uint2*)(g_A_hi + i) = make_uint2(h0, h1);
    *(uint2*)(g_A_lo + i) = make_uint2(l0, l1);
}

// ---------------------------------------------------------------------------
// Prepass: transpose W [1024][N] -> [N][1024] and split hi/lo.
// ---------------------------------------------------------------------------
template <int WHICH>
__global__ __launch_bounds__(256) void wprep_kernel(const float* __restrict__ W, int N)
{
    __shared__ float t[32][33];
    const int n0 = blockIdx.x * 32, k0 = blockIdx.y * 32;
    const int tx = threadIdx.x, ty = threadIdx.y;
    #pragma unroll
    for (int i = 0; i < 4; i++)
        t[ty + 8 * i][tx] = W[(size_t)(k0 + ty + 8 * i) * N + n0 + tx];
    __syncthreads();
    __nv_bfloat16* hi = (WHICH == 0) ? g_Wq_hi : g_Wp_hi;
    __nv_bfloat16* lo = (WHICH == 0) ? g_Wq_lo : g_Wp_lo;
    #pragma unroll
    for (int i = 0; i < 4; i++) {
        int n = n0 + ty + 8 * i, k = k0 + tx;
        float v = t[tx][ty + 8 * i];
        __nv_bfloat16 h = __float2bfloat16(v);
        hi[(size_t)n * D_MODEL + k] = h;
        lo[(size_t)n * D_MODEL + k] = __float2bfloat16(v - __bfloat162float(h));
    }
}

// ---------------------------------------------------------------------------
// bf16x3 GEMM via mma.sync.m16n8k16.
// __launch_bounds__(256, 2): cap 128 regs so 2 CTAs co-reside per SM
// (smem 2x80KB=160KB <= 228KB). Second CTA fills cp_wait/__syncthreads
// bubbles that capped tensor pipe at 50%.
// ---------------------------------------------------------------------------
#define GPITCH 80
#define TSZ    10240
#define BUFSZ  40960

template <bool IS_QKV>
__global__ __launch_bounds__(256, 2) void mma_gemm(float* __restrict__ Cparam)
{
    extern __shared__ char smem[];
    const int N = IS_QKV ? 3 * D_MODEL : D_MODEL;
    const __nv_bfloat16* BhiG = IS_QKV ? g_Wq_hi : g_Wp_hi;
    const __nv_bfloat16* BloG = IS_QKV ? g_Wq_lo : g_Wp_lo;
    float* C = IS_QKV ? (float*)g_qkv : Cparam;

    const int tid = threadIdx.x;
    const int wid = tid >> 5, lane = tid & 31;
    const int wm = wid & 3, wn = wid >> 2;
    const int g = lane >> 2, q = lane & 3;
    const int m0 = blockIdx.y * 128, n0 = blockIdx.x * 128;

    const char* srcs[4] = {
        (const char*)(g_A_hi + (size_t)m0 * D_MODEL),
        (const char*)(g_A_lo + (size_t)m0 * D_MODEL),
        (const char*)(BhiG + (size_t)n0 * D_MODEL),
        (const char*)(BloG + (size_t)n0 * D_MODEL) };

    const uint32_t sb = smem_to_u32(smem);
    float acc[2][8][4] = {};

    auto issue = [&](int c) {
        const uint32_t buf = sb + (c & 1) * BUFSZ;
        const size_t koff = (size_t)c * 64;
        #pragma unroll
        for (int i = 0; i < 8; i++) {
            int id = tid + i * 256;
            int t = id >> 9;
            int rem = id & 511;
            int row = rem >> 2, c16 = rem & 3;
            cp_async16(buf + t * TSZ + row * GPITCH + c16 * 16,
                       srcs[t] + (size_t)row * 2048 + koff + c16 * 16);
        }
        cp_commit();
    };

    issue(0);
    #pragma unroll 1
    for (int c = 0; c < 32; c++) {
        if (c + 1 < 32) { issue(c + 1); cp_wait<1>(); }
        else            { cp_wait<0>(); }
        __syncthreads();

        const char* buf = smem + (c & 1) * BUFSZ;
        #pragma unroll
        for (int ks = 0; ks < 2; ks++) {
            const int kb = ks * 32 + q * 4;
            uint32_t ah[2][4], al[2][4], bh[8][2], bl[8][2];
            #pragma unroll
            for (int am = 0; am < 2; am++) {
                const int r0 = wm * 32 + am * 16 + g;
                const char* p0 = buf + (size_t)r0 * GPITCH + kb;
                const char* p1 = buf + (size_t)(r0 + 8) * GPITCH + kb;
                ah[am][0] = *(const uint32_t*)(p0);
                ah[am][1] = *(const uint32_t*)(p1);
                ah[am][2] = *(const uint32_t*)(p0 + 16);
                ah[am][3] = *(const uint32_t*)(p1 + 16);
                al[am][0] = *(const uint32_t*)(p0 + TSZ);
                al[am][1] = *(const uint32_t*)(p1 + TSZ);
                al[am][2] = *(const uint32_t*)(p0 + TSZ + 16);
                al[am][3] = *(const uint32_t*)(p1 + TSZ + 16);
            }
            #pragma unroll
            for (int an = 0; an < 8; an++) {
                const int nr = wn * 64 + an * 8 + g;
                const char* pb = buf + 2 * TSZ + (size_t)nr * GPITCH + kb;
                bh[an][0] = *(const uint32_t*)(pb);
                bh[an][1] = *(const uint32_t*)(pb + 16);
                bl[an][0] = *(const uint32_t*)(pb + TSZ);
                bl[an][1] = *(const uint32_t*)(pb + TSZ + 16);
            }
            #pragma unroll
            for (int am = 0; am < 2; am++)
                #pragma unroll
                for (int an = 0; an < 8; an++) {
                    mma_bf16(acc[am][an], ah[am], bh[an]);
                    mma_bf16(acc[am][an], ah[am], bl[an]);
                    mma_bf16(acc[am][an], al[am], bh[an]);
                }
        }
        __syncthreads();
    }

    #pragma unroll
    for (int am = 0; am < 2; am++) {
        const int row = m0 + wm * 32 + am * 16 + g;
        #pragma unroll
        for (int an = 0; an < 8; an++) {
            const int col = n0 + wn * 64 + an * 8 + q * 2;
            *(float2*)(C + (size_t)row * N + col) =
                make_float2(acc[am][an][0], acc[am][an][1]);
            *(float2*)(C + (size_t)(row + 8) * N + col) =
                make_float2(acc[am][an][2], acc[am][an][3]);
        }
    }
}

// ---------------------------------------------------------------------------
// qkv_split: g_qkv fp32 -> planar bf16 hi/lo Q (x0.125), K, and V transposed.
// ---------------------------------------------------------------------------
__global__ __launch_bounds__(256) void qkv_split_kernel()
{
    __shared__ float vtile[64][65];
    const int bh = blockIdx.y;
    const int b = bh >> 4, h = bh & 15;
    const int i0 = blockIdx.x * 64;
    const int tid = threadIdx.x;

    const float* src = g_qkv + ((size_t)b * SEQ + i0) * (3 * D_MODEL) + h * DK;

    #pragma unroll
    for (int it = 0; it < 16; it++) {
        int idx = tid + it * 256;          // 0..4095
        int t = idx >> 6, d = idx & 63;
        const float* p = src + (size_t)t * (3 * D_MODEL) + d;
        float qv = p[0] * 0.125f;
        float kv = p[D_MODEL];
        float vv = p[2 * D_MODEL];
        size_t o = ((size_t)bh * SEQ + i0 + t) * DK + d;
        __nv_bfloat16 qh = __float2bfloat16(qv);
        g_Qh[o] = qh;
        g_Ql[o] = __float2bfloat16(qv - __bfloat162float(qh));
        __nv_bfloat16 kh = __float2bfloat16(kv);
        g_Kh[o] = kh;
        g_Kl[o] = __float2bfloat16(kv - __bfloat162float(kh));
        vtile[t][d] = vv;
    }
    __syncthreads();
    #pragma unroll
    for (int it = 0; it < 16; it++) {
        int idx = tid + it * 256;
        int d = idx >> 6, t = idx & 63;
        float vv = vtile[t][d];
        size_t o = ((size_t)bh * DK + d) * SEQ + i0 + t;
        __nv_bfloat16 vh = __float2bfloat16(vv);
        g_Vth[o] = vh;
        g_Vtl[o] = __float2bfloat16(vv - __bfloat162float(vh));
    }
}

// ---------------------------------------------------------------------------
// flash_mma: FA2-style bf16x3 attention on mma.sync (unchanged, passing).
// ---------------------------------------------------------------------------
#define KP 144

__global__ __launch_bounds__(128) void flash_mma()
{
    __shared__ __align__(16) char sKh[64 * KP];
    __shared__ __align__(16) char sKl[64 * KP];
    __shared__ __align__(16) char sVh[64 * KP];
    __shared__ __align__(16) char sVl[64 * KP];

    const int tid = threadIdx.x;
    const int w = tid >> 5, lane = tid & 31;
    const int g = lane >> 2, q = lane & 3;
    const int bh = blockIdx.y;
    const int b = bh >> 4, h = bh & 15;
    const int i0 = blockIdx.x * 64;
    const int rloc = 16 * w + g;

    uint32_t qh[4][4], ql[4][4];
    {
        const size_t base = ((size_t)bh * SEQ + i0 + rloc) * DK;
        #pragma unroll
        for (int ks = 0; ks < 4; ks++) {
            size_t e = base + ks * 16 + 2 * q;
            qh[ks][0] = *(const uint32_t*)(g_Qh + e);
            qh[ks][1] = *(const uint32_t*)(g_Qh + e + 8 * DK);
            qh[ks][2] = *(const uint32_t*)(g_Qh + e + 8);
            qh[ks][3] = *(const uint32_t*)(g_Qh + e + 8 * DK + 8);
            ql[ks][0] = *(const uint32_t*)(g_Ql + e);
            ql[ks][1] = *(const uint32_t*)(g_Ql + e + 8 * DK);
            ql[ks][2] = *(const uint32_t*)(g_Ql + e + 8);
            ql[ks][3] = *(const uint32_t*)(g_Ql + e + 8 * DK + 8);
        }
    }

    float o[8][4] = {};
    float m0 = -1e30f, m1 = -1e30f, l0 = 0.f, l1 = 0.f;

    const int jmax = blockIdx.x;
    #pragma unroll 1
    for (int jt = 0; jt <= jmax; jt++) {
        const int j0 = jt * 64;
        __syncthreads();
        {
            const __nv_bfloat16* gsrc[4] = {
                g_Kh  + ((size_t)bh * SEQ + j0) * DK,
                g_Kl  + ((size_t)bh * SEQ + j0) * DK,
                g_Vth + ((size_t)bh * DK) * SEQ + j0,
                g_Vtl + ((size_t)bh * DK) * SEQ + j0 };
            char* dsts[4] = { sKh, sKl, sVh, sVl };
            #pragma unroll
            for (int a = 0; a < 4; a++) {
                const size_t rstride = (a < 2) ? DK : SEQ;
                #pragma unroll
                for (int i = 0; i < 4; i++) {
                    int id = tid + i * 128;
                    int row = id >> 3, c8 = id & 7;
                    uint4 v = *(const uint4*)(gsrc[a] + (size_t)row * rstride + c8 * 8);
                    *(uint4*)(dsts[a] + row * KP + c8 * 16) = v;
                }
            }
        }
        __syncthreads();

        float s[8][4];
        #pragma unroll
        for (int an = 0; an < 8; an++) {
            s[an][0] = s[an][1] = s[an][2] = s[an][3] = 0.f;
            #pragma unroll
            for (int ks = 0; ks < 4; ks++) {
                const char* pK = sKh + (an * 8 + g) * KP + ks * 32 + q * 4;
                uint32_t b2h[2] = { *(const uint32_t*)pK, *(const uint32_t*)(pK + 16) };
                const char* pKl = sKl + (an * 8 + g) * KP + ks * 32 + q * 4;
                uint32_t b2l[2] = { *(const uint32_t*)pKl, *(const uint32_t*)(pKl + 16) };
                mma_bf16(s[an], qh[ks], b2h);
                mma_bf16(s[an], qh[ks], b2l);
                mma_bf16(s[an], ql[ks], b2h);
            }
        }

        if (jt == jmax) {
            #pragma unroll
            for (int an = 0; an < 8; an++) {
                int c0 = an * 8 + 2 * q, c1 = c0 + 1;
                if (c0 > rloc)     s[an][0] = -1e9f;
                if (c1 > rloc)     s[an][1] = -1e9f;
                if (c0 > rloc + 8) s[an][2] = -1e9f;
                if (c1 > rloc + 8) s[an][3] = -1e9f;
            }
        }

        float mx0 = -1e30f, mx1 = -1e30f;
        #pragma unroll
        for (int an = 0; an < 8; an++) {
            mx0 = fmaxf(mx0, fmaxf(s[an][0], s[an][1]));
            mx1 = fmaxf(mx1, fmaxf(s[an][2], s[an][3]));
        }
        mx0 = fmaxf(mx0, __shfl_xor_sync(0xFFFFFFFF, mx0, 1));
        mx0 = fmaxf(mx0, __shfl_xor_sync(0xFFFFFFFF, mx0, 2));
        mx1 = fmaxf(mx1, __shfl_xor_sync(0xFFFFFFFF, mx1, 1));
        mx1 = fmaxf(mx1, __shfl_xor_sync(0xFFFFFFFF, mx1, 2));
        float mn0 = fmaxf(m0, mx0), mn1 = fmaxf(m1, mx1);
        float a0 = __expf(m0 - mn0), a1 = __expf(m1 - mn1);
        float sum0 = 0.f, sum1 = 0.f;
        #pragma unroll
        for (int an = 0; an < 8; an++) {
            s[an][0] = __expf(s[an][0] - mn0);
            s[an][1] = __expf(s[an][1] - mn0);
            s[an][2] = __expf(s[an][2] - mn1);
            s[an][3] = __expf(s[an][3] - mn1);
            sum0 += s[an][0] + s[an][1];
            sum1 += s[an][2] + s[an][3];
        }
        sum0 += __shfl_xor_sync(0xFFFFFFFF, sum0, 1);
        sum0 += __shfl_xor_sync(0xFFFFFFFF, sum0, 2);
        sum1 += __shfl_xor_sync(0xFFFFFFFF, sum1, 1);
        sum1 += __shfl_xor_sync(0xFFFFFFFF, sum1, 2);
        l0 = l0 * a0 + sum0;  l1 = l1 * a1 + sum1;
        m0 = mn0;  m1 = mn1;
        #pragma unroll
        for (int an = 0; an < 8; an++) {
            o[an][0] *= a0; o[an][1] *= a0;
            o[an][2] *= a1; o[an][3] *= a1;
        }

        uint32_t ph[4][4], pl[4][4];
        #pragma unroll
        for (int kb = 0; kb < 4; kb++) {
            split2(s[2 * kb][0],     s[2 * kb][1],     ph[kb][0], pl[kb][0]);
            split2(s[2 * kb][2],     s[2 * kb][3],     ph[kb][1], pl[kb][1]);
            split2(s[2 * kb + 1][0], s[2 * kb + 1][1], ph[kb][2], pl[kb][2]);
            split2(s[2 * kb + 1][2], s[2 * kb + 1][3], ph[kb][3], pl[kb][3]);
        }

        #pragma unroll
        for (int an = 0; an < 8; an++) {
            #pragma unroll
            for (int kb = 0; kb < 4; kb++) {
                const char* pV = sVh + (an * 8 + g) * KP + kb * 32 + q * 4;
                uint32_t v2h[2] = { *(const uint32_t*)pV, *(const uint32_t*)(pV + 16) };
                const char* pVl = sVl + (an * 8 + g) * KP + kb * 32 + q * 4;
                uint32_t v2l[2] = { *(const uint32_t*)pVl, *(const uint32_t*)(pVl + 16) };
                mma_bf16(o[an], ph[kb], v2h);
                mma_bf16(o[an], ph[kb], v2l);
                mma_bf16(o[an], pl[kb], v2h);
            }
        }
    }

    const float li0 = 1.f / l0, li1 = 1.f / l1;
    const size_t row0 = (size_t)b * SEQ + i0 + rloc;
    #pragma unroll
    for (int an = 0; an < 8; an++) {
        const int col = h * DK + an * 8 + 2 * q;
        uint32_t hi, lo;
        split2(o[an][0] * li0, o[an][1] * li0, hi, lo);
        *(uint32_t*)(g_A_hi + row0 * D_MODEL + col) = hi;
        *(uint32_t*)(g_A_lo + row0 * D_MODEL + col) = lo;
        split2(o[an][2] * li1, o[an][3] * li1, hi, lo);
        *(uint32_t*)(g_A_hi + (row0 + 8) * D_MODEL + col) = hi;
        *(uint32_t*)(g_A_lo + (row0 + 8) * D_MODEL + col) = lo;
    }
}

// ---------------------------------------------------------------------------
extern "C" void kernel_launch(void* const* d_in, const int* in_sizes, int n_in,
                              void* d_out, int out_size)
{
    const float* x     = (const float*)d_in[0];
    const float* Wqkv  = (const float*)d_in[1];
    const float* Wproj = (const float*)d_in[2];
    float* out = (float*)d_out;

    const int GEMM_SMEM = 2 * BUFSZ;   // 80 KB
    cudaFuncSetAttribute(mma_gemm<true>,
                         cudaFuncAttributeMaxDynamicSharedMemorySize, GEMM_SMEM);
    cudaFuncSetAttribute(mma_gemm<false>,
                         cudaFuncAttributeMaxDynamicSharedMemorySize, GEMM_SMEM);

    // weight prepasses
    wprep_kernel<0><<<dim3(3 * D_MODEL / 32, D_MODEL / 32), dim3(32, 8)>>>(Wqkv, 3 * D_MODEL);
    wprep_kernel<1><<<dim3(D_MODEL / 32, D_MODEL / 32), dim3(32, 8)>>>(Wproj, D_MODEL);

    // x -> hi/lo
    aprep_kernel<<<(size_t)MTOT * D_MODEL / 4 / 256, 256>>>(x);

    // qkv = x @ W_qkv
    mma_gemm<true><<<dim3(3 * D_MODEL / 128, MTOT / 128), 256, GEMM_SMEM>>>(nullptr);

    // split qkv into flash operand layouts
    qkv_split_kernel<<<dim3(SEQ / 64, BH), 256>>>();

    // tensor-core flash attention -> writes g_A_hi/g_A_lo directly
    flash_mma<<<dim3(SEQ / 64, BH), 128>>>();

    // out = attn @ W_proj
    mma_gemm<false><<<dim3(D_MODEL / 128, MTOT / 128), 256, GEMM_SMEM>>>(out);
}

// round 9
// speedup vs baseline: 2.9793x; 1.0536x over previous
#include <cuda_runtime.h>
#include <cuda_bf16.h>
#include <cstdint>
#include <cstddef>

#define D_MODEL 1024
#define N_HEADS 16
#define DK      64
#define BATCH   4
#define SEQ     2048
#define MTOT    (BATCH * SEQ)     // 8192
#define BH      (BATCH * N_HEADS) // 64

// ---------------- device global scratch (no allocation APIs allowed) --------
__device__ float g_qkv[(size_t)MTOT * 3 * D_MODEL];              // 96 MB fp32
__device__ __nv_bfloat16 g_A_hi[(size_t)MTOT * D_MODEL];         // GEMM A input (x, then attn)
__device__ __nv_bfloat16 g_A_lo[(size_t)MTOT * D_MODEL];
__device__ __nv_bfloat16 g_Wq_hi[(size_t)3 * D_MODEL * D_MODEL]; // [3072][1024] K-major
__device__ __nv_bfloat16 g_Wq_lo[(size_t)3 * D_MODEL * D_MODEL];
__device__ __nv_bfloat16 g_Wp_hi[(size_t)D_MODEL * D_MODEL];
__device__ __nv_bfloat16 g_Wp_lo[(size_t)D_MODEL * D_MODEL];
// flash operands, per (b,h) planar
__device__ __nv_bfloat16 g_Qh[(size_t)BH * SEQ * DK];            // [bh][t][64], pre-scaled
__device__ __nv_bfloat16 g_Ql[(size_t)BH * SEQ * DK];
__device__ __nv_bfloat16 g_Kh[(size_t)BH * SEQ * DK];
__device__ __nv_bfloat16 g_Kl[(size_t)BH * SEQ * DK];
__device__ __nv_bfloat16 g_Vth[(size_t)BH * DK * SEQ];           // [bh][d][t]  (V transposed)
__device__ __nv_bfloat16 g_Vtl[(size_t)BH * DK * SEQ];

// ---------------- arch-agnostic PTX helpers (sm_80+ only) ------------------
__device__ __forceinline__ uint32_t smem_to_u32(const void* p) {
    uint32_t a;
    asm("{ .reg .u64 t; cvta.to.shared.u64 t, %1; cvt.u32.u64 %0, t; }"
        : "=r"(a) : "l"(p));
    return a;
}
__device__ __forceinline__ void cp_async16(uint32_t dst, const void* src) {
    asm volatile("cp.async.cg.shared.global [%0], [%1], 16;\n" :: "r"(dst), "l"(src));
}
__device__ __forceinline__ void cp_commit() {
    asm volatile("cp.async.commit_group;\n" ::: "memory");
}
template <int N>
__device__ __forceinline__ void cp_wait() {
    asm volatile("cp.async.wait_group %0;\n" :: "n"(N) : "memory");
}
__device__ __forceinline__ void mma_bf16(float* d, const uint32_t* a, const uint32_t* b) {
    asm volatile(
        "mma.sync.aligned.m16n8k16.row.col.f32.bf16.bf16.f32 "
        "{%0,%1,%2,%3}, {%4,%5,%6,%7}, {%8,%9}, {%0,%1,%2,%3};\n"
        : "+f"(d[0]), "+f"(d[1]), "+f"(d[2]), "+f"(d[3])
        : "r"(a[0]), "r"(a[1]), "r"(a[2]), "r"(a[3]), "r"(b[0]), "r"(b[1]));
}
// ldmatrix x4: 4 fragment regs in one instruction (sm_75+)
__device__ __forceinline__ void ldsm_x4(uint32_t* r, uint32_t addr) {
    asm volatile("ldmatrix.sync.aligned.m8n8.x4.shared.b16 {%0,%1,%2,%3}, [%4];"
        : "=r"(r[0]), "=r"(r[1]), "=r"(r[2]), "=r"(r[3]) : "r"(addr));
}
// split two fp32 into packed bf16x2 hi and lo-residual
__device__ __forceinline__ void split2(float x, float y, uint32_t& hi, uint32_t& lo) {
    __nv_bfloat16 hx = __float2bfloat16(x), hy = __float2bfloat16(y);
    __nv_bfloat16 lx = __float2bfloat16(x - __bfloat162float(hx));
    __nv_bfloat16 ly = __float2bfloat16(y - __bfloat162float(hy));
    __nv_bfloat162 hp(hx, hy), lp(lx, ly);
    hi = *(uint32_t*)&hp; lo = *(uint32_t*)&lp;
}

// ---------------------------------------------------------------------------
// Prepass: split fp32 x into bf16 hi/lo (GEMM A input).
// ---------------------------------------------------------------------------
__global__ __launch_bounds__(256) void aprep_kernel(const float* __restrict__ xin)
{
    size_t i = ((size_t)blockIdx.x * 256 + threadIdx.x) * 4;
    float4 v = *(const float4*)(xin + i);
    uint32_t h0, l0, h1, l1;
    split2(v.x, v.y, h0, l0);
    split2(v.z, v.w, h1, l1);
    *(uint2*)(g_A_hi + i) = make_uint2(h0, h1);
    *(uint2*)(g_A_lo + i) = make_uint2(l0, l1);
}

// ---------------------------------------------------------------------------
// Prepass: transpose W [1024][N] -> [N][1024] and split hi/lo.
// ---------------------------------------------------------------------------
template <int WHICH>
__global__ __launch_bounds__(256) void wprep_kernel(const float* __restrict__ W, int N)
{
    __shared__ float t[32][33];
    const int n0 = blockIdx.x * 32, k0 = blockIdx.y * 32;
    const int tx = threadIdx.x, ty = threadIdx.y;
    #pragma unroll
    for (int i = 0; i < 4; i++)
        t[ty + 8 * i][tx] = W[(size_t)(k0 + ty + 8 * i) * N + n0 + tx];
    __syncthreads();
    __nv_bfloat16* hi = (WHICH == 0) ? g_Wq_hi : g_Wp_hi;
    __nv_bfloat16* lo = (WHICH == 0) ? g_Wq_lo : g_Wp_lo;
    #pragma unroll
    for (int i = 0; i < 4; i++) {
        int n = n0 + ty + 8 * i, k = k0 + tx;
        float v = t[tx][ty + 8 * i];
        __nv_bfloat16 h = __float2bfloat16(v);
        hi[(size_t)n * D_MODEL + k] = h;
        lo[(size_t)n * D_MODEL + k] = __float2bfloat16(v - __bfloat162float(h));
    }
}

// ---------------------------------------------------------------------------
// bf16x3 GEMM via mma.sync.m16n8k16 + ldmatrix fragment loads.
// 2 CTAs/SM (reg cap 128). Fragment loads: ldmatrix.x4 (12 per K16-step vs 48 LDS).
// ---------------------------------------------------------------------------
#define GPITCH 80
#define TSZ    10240
#define BUFSZ  40960

template <bool IS_QKV>
__global__ __launch_bounds__(256, 2) void mma_gemm(float* __restrict__ Cparam)
{
    extern __shared__ char smem[];
    const int N = IS_QKV ? 3 * D_MODEL : D_MODEL;
    const __nv_bfloat16* BhiG = IS_QKV ? g_Wq_hi : g_Wp_hi;
    const __nv_bfloat16* BloG = IS_QKV ? g_Wq_lo : g_Wp_lo;
    float* C = IS_QKV ? (float*)g_qkv : Cparam;

    const int tid = threadIdx.x;
    const int wid = tid >> 5, lane = tid & 31;
    const int wm = wid & 3, wn = wid >> 2;
    const int g = lane >> 2, q = lane & 3;
    const int m0 = blockIdx.y * 128, n0 = blockIdx.x * 128;

    const char* srcs[4] = {
        (const char*)(g_A_hi + (size_t)m0 * D_MODEL),
        (const char*)(g_A_lo + (size_t)m0 * D_MODEL),
        (const char*)(BhiG + (size_t)n0 * D_MODEL),
        (const char*)(BloG + (size_t)n0 * D_MODEL) };

    const uint32_t sb = smem_to_u32(smem);

    // ldmatrix per-lane base offsets (within a buffer)
    // A (m16k16 x4): lanes 0-15 -> rows 0..15 @k[0:8), lanes 16-31 -> same rows @k[8:16)
    const uint32_t aOff = (uint32_t)(wm * 32 + (lane & 15)) * GPITCH + (lane >> 4) * 16;
    // B (two n8k16 frags per x4): row = wn*64 + pair*16 + ((lane>>4)&1)*8 + (lane&7),
    // col16 = ((lane>>3)&1)*16
    const uint32_t bOff = 2 * TSZ +
        (uint32_t)(wn * 64 + ((lane >> 4) & 1) * 8 + (lane & 7)) * GPITCH +
        ((lane >> 3) & 1) * 16;

    float acc[2][8][4] = {};

    auto issue = [&](int c) {
        const uint32_t buf = sb + (c & 1) * BUFSZ;
        const size_t koff = (size_t)c * 64;
        #pragma unroll
        for (int i = 0; i < 8; i++) {
            int id = tid + i * 256;
            int t = id >> 9;
            int rem = id & 511;
            int row = rem >> 2, c16 = rem & 3;
            cp_async16(buf + t * TSZ + row * GPITCH + c16 * 16,
                       srcs[t] + (size_t)row * 2048 + koff + c16 * 16);
        }
        cp_commit();
    };

    issue(0);
    #pragma unroll 1
    for (int c = 0; c < 32; c++) {
        if (c + 1 < 32) { issue(c + 1); cp_wait<1>(); }
        else            { cp_wait<0>(); }
        __syncthreads();

        const uint32_t buf = sb + (c & 1) * BUFSZ;
        #pragma unroll
        for (int ks = 0; ks < 2; ks++) {
            const uint32_t ksb = ks * 32;
            uint32_t ah[2][4], al[2][4], bh[4][4], bl[4][4];
            #pragma unroll
            for (int am = 0; am < 2; am++) {
                const uint32_t a = buf + aOff + (uint32_t)am * 16 * GPITCH + ksb;
                ldsm_x4(ah[am], a);
                ldsm_x4(al[am], a + TSZ);
            }
            #pragma unroll
            for (int j = 0; j < 4; j++) {
                const uint32_t a = buf + bOff + (uint32_t)j * 16 * GPITCH + ksb;
                ldsm_x4(bh[j], a);
                ldsm_x4(bl[j], a + TSZ);
            }
            #pragma unroll
            for (int am = 0; am < 2; am++)
                #pragma unroll
                for (int j = 0; j < 4; j++) {
                    mma_bf16(acc[am][2 * j],     ah[am], &bh[j][0]);
                    mma_bf16(acc[am][2 * j],     ah[am], &bl[j][0]);
                    mma_bf16(acc[am][2 * j],     al[am], &bh[j][0]);
                    mma_bf16(acc[am][2 * j + 1], ah[am], &bh[j][2]);
                    mma_bf16(acc[am][2 * j + 1], ah[am], &bl[j][2]);
                    mma_bf16(acc[am][2 * j + 1], al[am], &bh[j][2]);
                }
        }
        __syncthreads();
    }

    #pragma unroll
    for (int am = 0; am < 2; am++) {
        const int row = m0 + wm * 32 + am * 16 + g;
        #pragma unroll
        for (int an = 0; an < 8; an++) {
            const int col = n0 + wn * 64 + an * 8 + q * 2;
            *(float2*)(C + (size_t)row * N + col) =
                make_float2(acc[am][an][0], acc[am][an][1]);
            *(float2*)(C + (size_t)(row + 8) * N + col) =
                make_float2(acc[am][an][2], acc[am][an][3]);
        }
    }
}

// ---------------------------------------------------------------------------
// qkv_split: g_qkv fp32 -> planar bf16 hi/lo Q (x0.125), K, and V transposed.
// ---------------------------------------------------------------------------
__global__ __launch_bounds__(256) void qkv_split_kernel()
{
    __shared__ float vtile[64][65];
    const int bh = blockIdx.y;
    const int b = bh >> 4, h = bh & 15;
    const int i0 = blockIdx.x * 64;
    const int tid = threadIdx.x;

    const float* src = g_qkv + ((size_t)b * SEQ + i0) * (3 * D_MODEL) + h * DK;

    #pragma unroll
    for (int it = 0; it < 16; it++) {
        int idx = tid + it * 256;          // 0..4095
        int t = idx >> 6, d = idx & 63;
        const float* p = src + (size_t)t * (3 * D_MODEL) + d;
        float qv = p[0] * 0.125f;
        float kv = p[D_MODEL];
        float vv = p[2 * D_MODEL];
        size_t o = ((size_t)bh * SEQ + i0 + t) * DK + d;
        __nv_bfloat16 qh = __float2bfloat16(qv);
        g_Qh[o] = qh;
        g_Ql[o] = __float2bfloat16(qv - __bfloat162float(qh));
        __nv_bfloat16 kh = __float2bfloat16(kv);
        g_Kh[o] = kh;
        g_Kl[o] = __float2bfloat16(kv - __bfloat162float(kh));
        vtile[t][d] = vv;
    }
    __syncthreads();
    #pragma unroll
    for (int it = 0; it < 16; it++) {
        int idx = tid + it * 256;
        int d = idx >> 6, t = idx & 63;
        float vv = vtile[t][d];
        size_t o = ((size_t)bh * DK + d) * SEQ + i0 + t;
        __nv_bfloat16 vh = __float2bfloat16(vv);
        g_Vth[o] = vh;
        g_Vtl[o] = __float2bfloat16(vv - __bfloat162float(vh));
    }
}

// ---------------------------------------------------------------------------
// flash_mma: FA2-style bf16x3 attention on mma.sync + ldmatrix fragment loads.
// ---------------------------------------------------------------------------
#define KP 144

__global__ __launch_bounds__(128) void flash_mma()
{
    __shared__ __align__(16) char sKh[64 * KP];
    __shared__ __align__(16) char sKl[64 * KP];
    __shared__ __align__(16) char sVh[64 * KP];
    __shared__ __align__(16) char sVl[64 * KP];

    const int tid = threadIdx.x;
    const int w = tid >> 5, lane = tid & 31;
    const int g = lane >> 2, q = lane & 3;
    const int bh = blockIdx.y;
    const int b = bh >> 4, h = bh & 15;
    const int i0 = blockIdx.x * 64;
    const int rloc = 16 * w + g;

    // ldmatrix per-lane base offsets for B-style frags (pair of n8k16 per x4):
    const uint32_t bRow = (uint32_t)(((lane >> 4) & 1) * 8 + (lane & 7)) * KP +
                          ((lane >> 3) & 1) * 16;
    const uint32_t kBaseH = smem_to_u32(sKh) + bRow;
    const uint32_t kBaseL = smem_to_u32(sKl) + bRow;
    const uint32_t vBaseH = smem_to_u32(sVh) + bRow;
    const uint32_t vBaseL = smem_to_u32(sVl) + bRow;

    uint32_t qh[4][4], ql[4][4];
    {
        const size_t base = ((size_t)bh * SEQ + i0 + rloc) * DK;
        #pragma unroll
        for (int ks = 0; ks < 4; ks++) {
            size_t e = base + ks * 16 + 2 * q;
            qh[ks][0] = *(const uint32_t*)(g_Qh + e);
            qh[ks][1] = *(const uint32_t*)(g_Qh + e + 8 * DK);
            qh[ks][2] = *(const uint32_t*)(g_Qh + e + 8);
            qh[ks][3] = *(const uint32_t*)(g_Qh + e + 8 * DK + 8);
            ql[ks][0] = *(const uint32_t*)(g_Ql + e);
            ql[ks][1] = *(const uint32_t*)(g_Ql + e + 8 * DK);
            ql[ks][2] = *(const uint32_t*)(g_Ql + e + 8);
            ql[ks][3] = *(const uint32_t*)(g_Ql + e + 8 * DK + 8);
        }
    }

    float o[8][4] = {};
    float m0 = -1e30f, m1 = -1e30f, l0 = 0.f, l1 = 0.f;

    const int jmax = blockIdx.x;
    #pragma unroll 1
    for (int jt = 0; jt <= jmax; jt++) {
        const int j0 = jt * 64;
        __syncthreads();
        {
            const __nv_bfloat16* gsrc[4] = {
                g_Kh  + ((size_t)bh * SEQ + j0) * DK,
                g_Kl  + ((size_t)bh * SEQ + j0) * DK,
                g_Vth + ((size_t)bh * DK) * SEQ + j0,
                g_Vtl + ((size_t)bh * DK) * SEQ + j0 };
            char* dsts[4] = { sKh, sKl, sVh, sVl };
            #pragma unroll
            for (int a = 0; a < 4; a++) {
                const size_t rstride = (a < 2) ? DK : SEQ;
                #pragma unroll
                for (int i = 0; i < 4; i++) {
                    int id = tid + i * 128;
                    int row = id >> 3, c8 = id & 7;
                    uint4 v = *(const uint4*)(gsrc[a] + (size_t)row * rstride + c8 * 8);
                    *(uint4*)(dsts[a] + row * KP + c8 * 16) = v;
                }
            }
        }
        __syncthreads();

        // S = Qh*Kh + Qh*Kl + Ql*Kh   (ldmatrix pair loads: an=2j, 2j+1)
        float s[8][4];
        #pragma unroll
        for (int an = 0; an < 8; an++)
            s[an][0] = s[an][1] = s[an][2] = s[an][3] = 0.f;
        #pragma unroll
        for (int ks = 0; ks < 4; ks++) {
            #pragma unroll
            for (int j = 0; j < 4; j++) {
                uint32_t kh4[4], kl4[4];
                const uint32_t off = (uint32_t)j * 16 * KP + ks * 32;
                ldsm_x4(kh4, kBaseH + off);
                ldsm_x4(kl4, kBaseL + off);
                mma_bf16(s[2 * j],     qh[ks], &kh4[0]);
                mma_bf16(s[2 * j],     qh[ks], &kl4[0]);
                mma_bf16(s[2 * j],     ql[ks], &kh4[0]);
                mma_bf16(s[2 * j + 1], qh[ks], &kh4[2]);
                mma_bf16(s[2 * j + 1], qh[ks], &kl4[2]);
                mma_bf16(s[2 * j + 1], ql[ks], &kh4[2]);
            }
        }

        if (jt == jmax) {
            #pragma unroll
            for (int an = 0; an < 8; an++) {
                int c0 = an * 8 + 2 * q, c1 = c0 + 1;
                if (c0 > rloc)     s[an][0] = -1e9f;
                if (c1 > rloc)     s[an][1] = -1e9f;
                if (c0 > rloc + 8) s[an][2] = -1e9f;
                if (c1 > rloc + 8) s[an][3] = -1e9f;
            }
        }

        float mx0 = -1e30f, mx1 = -1e30f;
        #pragma unroll
        for (int an = 0; an < 8; an++) {
            mx0 = fmaxf(mx0, fmaxf(s[an][0], s[an][1]));
            mx1 = fmaxf(mx1, fmaxf(s[an][2], s[an][3]));
        }
        mx0 = fmaxf(mx0, __shfl_xor_sync(0xFFFFFFFF, mx0, 1));
        mx0 = fmaxf(mx0, __shfl_xor_sync(0xFFFFFFFF, mx0, 2));
        mx1 = fmaxf(mx1, __shfl_xor_sync(0xFFFFFFFF, mx1, 1));
        mx1 = fmaxf(mx1, __shfl_xor_sync(0xFFFFFFFF, mx1, 2));
        float mn0 = fmaxf(m0, mx0), mn1 = fmaxf(m1, mx1);
        float a0 = __expf(m0 - mn0), a1 = __expf(m1 - mn1);
        float sum0 = 0.f, sum1 = 0.f;
        #pragma unroll
        for (int an = 0; an < 8; an++) {
            s[an][0] = __expf(s[an][0] - mn0);
            s[an][1] = __expf(s[an][1] - mn0);
            s[an][2] = __expf(s[an][2] - mn1);
            s[an][3] = __expf(s[an][3] - mn1);
            sum0 += s[an][0] + s[an][1];
            sum1 += s[an][2] + s[an][3];
        }
        sum0 += __shfl_xor_sync(0xFFFFFFFF, sum0, 1);
        sum0 += __shfl_xor_sync(0xFFFFFFFF, sum0, 2);
        sum1 += __shfl_xor_sync(0xFFFFFFFF, sum1, 1);
        sum1 += __shfl_xor_sync(0xFFFFFFFF, sum1, 2);
        l0 = l0 * a0 + sum0;  l1 = l1 * a1 + sum1;
        m0 = mn0;  m1 = mn1;
        #pragma unroll
        for (int an = 0; an < 8; an++) {
            o[an][0] *= a0; o[an][1] *= a0;
            o[an][2] *= a1; o[an][3] *= a1;
        }

        uint32_t ph[4][4], pl[4][4];
        #pragma unroll
        for (int kb = 0; kb < 4; kb++) {
            split2(s[2 * kb][0],     s[2 * kb][1],     ph[kb][0], pl[kb][0]);
            split2(s[2 * kb][2],     s[2 * kb][3],     ph[kb][1], pl[kb][1]);
            split2(s[2 * kb + 1][0], s[2 * kb + 1][1], ph[kb][2], pl[kb][2]);
            split2(s[2 * kb + 1][2], s[2 * kb + 1][3], ph[kb][3], pl[kb][3]);
        }

        // O += Ph*Vh + Ph*Vl + Pl*Vh
        #pragma unroll
        for (int kb = 0; kb < 4; kb++) {
            #pragma unroll
            for (int j = 0; j < 4; j++) {
                uint32_t vh4[4], vl4[4];
                const uint32_t off = (uint32_t)j * 16 * KP + kb * 32;
                ldsm_x4(vh4, vBaseH + off);
                ldsm_x4(vl4, vBaseL + off);
                mma_bf16(o[2 * j],     ph[kb], &vh4[0]);
                mma_bf16(o[2 * j],     ph[kb], &vl4[0]);
                mma_bf16(o[2 * j],     pl[kb], &vh4[0]);
                mma_bf16(o[2 * j + 1], ph[kb], &vh4[2]);
                mma_bf16(o[2 * j + 1], ph[kb], &vl4[2]);
                mma_bf16(o[2 * j + 1], pl[kb], &vh4[2]);
            }
        }
    }

    const float li0 = 1.f / l0, li1 = 1.f / l1;
    const size_t row0 = (size_t)b * SEQ + i0 + rloc;
    #pragma unroll
    for (int an = 0; an < 8; an++) {
        const int col = h * DK + an * 8 + 2 * q;
        uint32_t hi, lo;
        split2(o[an][0] * li0, o[an][1] * li0, hi, lo);
        *(uint32_t*)(g_A_hi + row0 * D_MODEL + col) = hi;
        *(uint32_t*)(g_A_lo + row0 * D_MODEL + col) = lo;
        split2(o[an][2] * li1, o[an][3] * li1, hi, lo);
        *(uint32_t*)(g_A_hi + (row0 + 8) * D_MODEL + col) = hi;
        *(uint32_t*)(g_A_lo + (row0 + 8) * D_MODEL + col) = lo;
    }
}

// ---------------------------------------------------------------------------
extern "C" void kernel_launch(void* const* d_in, const int* in_sizes, int n_in,
                              void* d_out, int out_size)
{
    const float* x     = (const float*)d_in[0];
    const float* Wqkv  = (const float*)d_in[1];
    const float* Wproj = (const float*)d_in[2];
    float* out = (float*)d_out;

    const int GEMM_SMEM = 2 * BUFSZ;   // 80 KB
    cudaFuncSetAttribute(mma_gemm<true>,
                         cudaFuncAttributeMaxDynamicSharedMemorySize, GEMM_SMEM);
    cudaFuncSetAttribute(mma_gemm<false>,
                         cudaFuncAttributeMaxDynamicSharedMemorySize, GEMM_SMEM);

    // weight prepasses
    wprep_kernel<0><<<dim3(3 * D_MODEL / 32, D_MODEL / 32), dim3(32, 8)>>>(Wqkv, 3 * D_MODEL);
    wprep_kernel<1><<<dim3(D_MODEL / 32, D_MODEL / 32), dim3(32, 8)>>>(Wproj, D_MODEL);

    // x -> hi/lo
    aprep_kernel<<<(size_t)MTOT * D_MODEL / 4 / 256, 256>>>(x);

    // qkv = x @ W_qkv
    mma_gemm<true><<<dim3(3 * D_MODEL / 128, MTOT / 128), 256, GEMM_SMEM>>>(nullptr);

    // split qkv into flash operand layouts
    qkv_split_kernel<<<dim3(SEQ / 64, BH), 256>>>();

    // tensor-core flash attention -> writes g_A_hi/g_A_lo directly
    flash_mma<<<dim3(SEQ / 64, BH), 128>>>();

    // out = attn @ W_proj
    mma_gemm<false><<<dim3(D_MODEL / 128, MTOT / 128), 256, GEMM_SMEM>>>(out);
}

// round 11
// speedup vs baseline: 3.1509x; 1.0576x over previous
#include <cuda_runtime.h>
#include <cuda_bf16.h>
#include <cstdint>
#include <cstddef>

#define D_MODEL 1024
#define N_HEADS 16
#define DK      64
#define BATCH   4
#define SEQ     2048
#define MTOT    (BATCH * SEQ)     // 8192
#define BH      (BATCH * N_HEADS) // 64

// ---------------- device global scratch (no allocation APIs allowed) --------
__device__ __nv_bfloat16 g_A_hi[(size_t)MTOT * D_MODEL];         // GEMM A input (x, then attn)
__device__ __nv_bfloat16 g_A_lo[(size_t)MTOT * D_MODEL];
__device__ __nv_bfloat16 g_Wq_hi[(size_t)3 * D_MODEL * D_MODEL]; // [3072][1024] K-major
__device__ __nv_bfloat16 g_Wq_lo[(size_t)3 * D_MODEL * D_MODEL];
__device__ __nv_bfloat16 g_Wp_hi[(size_t)D_MODEL * D_MODEL];
__device__ __nv_bfloat16 g_Wp_lo[(size_t)D_MODEL * D_MODEL];
// flash operands, per (b,h) planar  (written directly by QKV GEMM epilogue)
__device__ __nv_bfloat16 g_Qh[(size_t)BH * SEQ * DK];            // [bh][t][64], pre-scaled
__device__ __nv_bfloat16 g_Ql[(size_t)BH * SEQ * DK];
__device__ __nv_bfloat16 g_Kh[(size_t)BH * SEQ * DK];
__device__ __nv_bfloat16 g_Kl[(size_t)BH * SEQ * DK];
__device__ __nv_bfloat16 g_Vh[(size_t)BH * SEQ * DK];            // [bh][t][64] (pre-transpose)
__device__ __nv_bfloat16 g_Vl[(size_t)BH * SEQ * DK];
__device__ __nv_bfloat16 g_Vth[(size_t)BH * DK * SEQ];           // [bh][d][t]  (V transposed)
__device__ __nv_bfloat16 g_Vtl[(size_t)BH * DK * SEQ];

// ---------------- arch-agnostic PTX helpers (sm_80+ only) ------------------
__device__ __forceinline__ uint32_t smem_to_u32(const void* p) {
    uint32_t a;
    asm("{ .reg .u64 t; cvta.to.shared.u64 t, %1; cvt.u32.u64 %0, t; }"
        : "=r"(a) : "l"(p));
    return a;
}
__device__ __forceinline__ void cp_async16(uint32_t dst, const void* src) {
    asm volatile("cp.async.cg.shared.global [%0], [%1], 16;\n" :: "r"(dst), "l"(src));
}
__device__ __forceinline__ void cp_commit() {
    asm volatile("cp.async.commit_group;\n" ::: "memory");
}
template <int N>
__device__ __forceinline__ void cp_wait() {
    asm volatile("cp.async.wait_group %0;\n" :: "n"(N) : "memory");
}
__device__ __forceinline__ void mma_bf16(float* d, const uint32_t* a, const uint32_t* b) {
    asm volatile(
        "mma.sync.aligned.m16n8k16.row.col.f32.bf16.bf16.f32 "
        "{%0,%1,%2,%3}, {%4,%5,%6,%7}, {%8,%9}, {%0,%1,%2,%3};\n"
        : "+f"(d[0]), "+f"(d[1]), "+f"(d[2]), "+f"(d[3])
        : "r"(a[0]), "r"(a[1]), "r"(a[2]), "r"(a[3]), "r"(b[0]), "r"(b[1]));
}
// ldmatrix x4: 4 fragment regs in one instruction (sm_75+)
__device__ __forceinline__ void ldsm_x4(uint32_t* r, uint32_t addr) {
    asm volatile("ldmatrix.sync.aligned.m8n8.x4.shared.b16 {%0,%1,%2,%3}, [%4];"
        : "=r"(r[0]), "=r"(r[1]), "=r"(r[2]), "=r"(r[3]) : "r"(addr));
}
// split two fp32 into packed bf16x2 hi and lo-residual
__device__ __forceinline__ void split2(float x, float y, uint32_t& hi, uint32_t& lo) {
    __nv_bfloat16 hx = __float2bfloat16(x), hy = __float2bfloat16(y);
    __nv_bfloat16 lx = __float2bfloat16(x - __bfloat162float(hx));
    __nv_bfloat16 ly = __float2bfloat16(y - __bfloat162float(hy));
    __nv_bfloat162 hp(hx, hy), lp(lx, ly);
    hi = *(uint32_t*)&hp; lo = *(uint32_t*)&lp;
}

// ---------------------------------------------------------------------------
// Prepass: split fp32 x into bf16 hi/lo (GEMM A input).
// ---------------------------------------------------------------------------
__global__ __launch_bounds__(256) void aprep_kernel(const float* __restrict__ xin)
{
    size_t i = ((size_t)blockIdx.x * 256 + threadIdx.x) * 4;
    float4 v = *(const float4*)(xin + i);
    uint32_t h0, l0, h1, l1;
    split2(v.x, v.y, h0, l0);
    split2(v.z, v.w, h1, l1);
    *(uint2*)(g_A_hi + i) = make_uint2(h0, h1);
    *(uint2*)(g_A_lo + i) = make_uint2(l0, l1);
}

// ---------------------------------------------------------------------------
// Prepass: transpose W [1024][N] -> [N][1024] and split hi/lo.
// ---------------------------------------------------------------------------
template <int WHICH>
__global__ __launch_bounds__(256) void wprep_kernel(const float* __restrict__ W, int N)
{
    __shared__ float t[32][33];
    const int n0 = blockIdx.x * 32, k0 = blockIdx.y * 32;
    const int tx = threadIdx.x, ty = threadIdx.y;
    #pragma unroll
    for (int i = 0; i < 4; i++)
        t[ty + 8 * i][tx] = W[(size_t)(k0 + ty + 8 * i) * N + n0 + tx];
    __syncthreads();
    __nv_bfloat16* hi = (WHICH == 0) ? g_Wq_hi : g_Wp_hi;
    __nv_bfloat16* lo = (WHICH == 0) ? g_Wq_lo : g_Wp_lo;
    #pragma unroll
    for (int i = 0; i < 4; i++) {
        int n = n0 + ty + 8 * i, k = k0 + tx;
        float v = t[tx][ty + 8 * i];
        __nv_bfloat16 h = __float2bfloat16(v);
        hi[(size_t)n * D_MODEL + k] = h;
        lo[(size_t)n * D_MODEL + k] = __float2bfloat16(v - __bfloat162float(h));
    }
}

// ---------------------------------------------------------------------------
// bf16x3 GEMM via mma.sync.m16n8k16 + ldmatrix.
// IS_QKV: fused epilogue writes planar bf16 hi/lo Q (x0.125) / K / V directly.
// ---------------------------------------------------------------------------
#define GPITCH 80
#define TSZ    10240
#define BUFSZ  40960

template <bool IS_QKV>
__global__ __launch_bounds__(256, 2) void mma_gemm(float* __restrict__ Cparam)
{
    extern __shared__ char smem[];
    const int N = IS_QKV ? 3 * D_MODEL : D_MODEL;
    const __nv_bfloat16* BhiG = IS_QKV ? g_Wq_hi : g_Wp_hi;
    const __nv_bfloat16* BloG = IS_QKV ? g_Wq_lo : g_Wp_lo;

    const int tid = threadIdx.x;
    const int wid = tid >> 5, lane = tid & 31;
    const int wm = wid & 3, wn = wid >> 2;
    const int g = lane >> 2, q = lane & 3;
    const int m0 = blockIdx.y * 128, n0 = blockIdx.x * 128;

    const char* srcs[4] = {
        (const char*)(g_A_hi + (size_t)m0 * D_MODEL),
        (const char*)(g_A_lo + (size_t)m0 * D_MODEL),
        (const char*)(BhiG + (size_t)n0 * D_MODEL),
        (const char*)(BloG + (size_t)n0 * D_MODEL) };

    const uint32_t sb = smem_to_u32(smem);

    const uint32_t aOff = (uint32_t)(wm * 32 + (lane & 15)) * GPITCH + (lane >> 4) * 16;
    const uint32_t bOff = 2 * TSZ +
        (uint32_t)(wn * 64 + ((lane >> 4) & 1) * 8 + (lane & 7)) * GPITCH +
        ((lane >> 3) & 1) * 16;

    float acc[2][8][4] = {};

    auto issue = [&](int c) {
        const uint32_t buf = sb + (c & 1) * BUFSZ;
        const size_t koff = (size_t)c * 64;
        #pragma unroll
        for (int i = 0; i < 8; i++) {
            int id = tid + i * 256;
            int t = id >> 9;
            int rem = id & 511;
            int row = rem >> 2, c16 = rem & 3;
            cp_async16(buf + t * TSZ + row * GPITCH + c16 * 16,
                       srcs[t] + (size_t)row * 2048 + koff + c16 * 16);
        }
        cp_commit();
    };

    issue(0);
    #pragma unroll 1
    for (int c = 0; c < 32; c++) {
        if (c + 1 < 32) { issue(c + 1); cp_wait<1>(); }
        else            { cp_wait<0>(); }
        __syncthreads();

        const uint32_t buf = sb + (c & 1) * BUFSZ;
        #pragma unroll
        for (int ks = 0; ks < 2; ks++) {
            const uint32_t ksb = ks * 32;
            uint32_t ah[2][4], al[2][4], bh[4][4], bl[4][4];
            #pragma unroll
            for (int am = 0; am < 2; am++) {
                const uint32_t a = buf + aOff + (uint32_t)am * 16 * GPITCH + ksb;
                ldsm_x4(ah[am], a);
                ldsm_x4(al[am], a + TSZ);
            }
            #pragma unroll
            for (int j = 0; j < 4; j++) {
                const uint32_t a = buf + bOff + (uint32_t)j * 16 * GPITCH + ksb;
                ldsm_x4(bh[j], a);
                ldsm_x4(bl[j], a + TSZ);
            }
            #pragma unroll
            for (int am = 0; am < 2; am++)
                #pragma unroll
                for (int j = 0; j < 4; j++) {
                    mma_bf16(acc[am][2 * j],     ah[am], &bh[j][0]);
                    mma_bf16(acc[am][2 * j],     ah[am], &bl[j][0]);
                    mma_bf16(acc[am][2 * j],     al[am], &bh[j][0]);
                    mma_bf16(acc[am][2 * j + 1], ah[am], &bh[j][2]);
                    mma_bf16(acc[am][2 * j + 1], ah[am], &bl[j][2]);
                    mma_bf16(acc[am][2 * j + 1], al[am], &bh[j][2]);
                }
        }
        __syncthreads();
    }

    if (IS_QKV) {
        // fused epilogue: split hi/lo, write planar [bh][t][64]
        const int region = n0 >> 10;                         // 0=Q, 1=K, 2=V
        __nv_bfloat16* dsthi = (region == 0) ? g_Qh : (region == 1) ? g_Kh : g_Vh;
        __nv_bfloat16* dstlo = (region == 0) ? g_Ql : (region == 1) ? g_Kl : g_Vl;
        const float scale = (region == 0) ? 0.125f : 1.0f;
        const int crbase = (n0 & 1023) + wn * 64;
        const int b = m0 >> 11;                              // batch (tiles don't span)
        #pragma unroll
        for (int am = 0; am < 2; am++) {
            const int t0 = (m0 & 2047) + wm * 32 + am * 16 + g;
            #pragma unroll
            for (int an = 0; an < 8; an++) {
                const int cr = crbase + an * 8 + q * 2;
                const int h = cr >> 6, d = cr & 63;
                const size_t base = (((size_t)(b * 16 + h)) * SEQ + t0) * DK + d;
                uint32_t hi, lo;
                split2(acc[am][an][0] * scale, acc[am][an][1] * scale, hi, lo);
                *(uint32_t*)(dsthi + base) = hi;
                *(uint32_t*)(dstlo + base) = lo;
                split2(acc[am][an][2] * scale, acc[am][an][3] * scale, hi, lo);
                *(uint32_t*)(dsthi + base + 8 * DK) = hi;
                *(uint32_t*)(dstlo + base + 8 * DK) = lo;
            }
        }
    } else {
        #pragma unroll
        for (int am = 0; am < 2; am++) {
            const int row = m0 + wm * 32 + am * 16 + g;
            #pragma unroll
            for (int an = 0; an < 8; an++) {
                const int col = n0 + wn * 64 + an * 8 + q * 2;
                *(float2*)(Cparam + (size_t)row * N + col) =
                    make_float2(acc[am][an][0], acc[am][an][1]);
                *(float2*)(Cparam + (size_t)(row + 8) * N + col) =
                    make_float2(acc[am][an][2], acc[am][an][3]);
            }
        }
    }
}

// ---------------------------------------------------------------------------
// vtrans: bf16 V [bh][t][64] -> V^T [bh][d][2048] (hi and lo).
// ---------------------------------------------------------------------------
__global__ __launch_bounds__(256) void vtrans_kernel()
{
    __shared__ __nv_bfloat16 th[64][66];
    __shared__ __nv_bfloat16 tl[64][66];
    const int bh = blockIdx.y;
    const int i0 = blockIdx.x * 64;
    const int tid = threadIdx.x;

    #pragma unroll
    for (int it = 0; it < 16; it++) {
        int idx = tid + it * 256;
        int t = idx >> 6, d = idx & 63;
        size_t src = ((size_t)bh * SEQ + i0 + t) * DK + d;
        th[t][d] = g_Vh[src];
        tl[t][d] = g_Vl[src];
    }
    __syncthreads();
    #pragma unroll
    for (int it = 0; it < 16; it++) {
        int idx = tid + it * 256;
        int d = idx >> 6, t = idx & 63;
        size_t dst = ((size_t)bh * DK + d) * SEQ + i0 + t;
        g_Vth[dst] = th[t][d];
        g_Vtl[dst] = tl[t][d];
    }
}

// ---------------------------------------------------------------------------
// flash_mma: FA2-style bf16x3 attention, ldmatrix + cp.async double buffer.
// ---------------------------------------------------------------------------
#define KP   144
#define FARR 9216     // 64 * KP
#define FBUF 36864    // 4 arrays (Kh, Kl, Vh, Vl)

__global__ __launch_bounds__(128) void flash_mma()
{
    extern __shared__ char fsm[];
    const uint32_t fb = smem_to_u32(fsm);

    const int tid = threadIdx.x;
    const int w = tid >> 5, lane = tid & 31;
    const int g = lane >> 2, q = lane & 3;
    const int bh = blockIdx.y;
    const int b = bh >> 4, h = bh & 15;
    const int i0 = blockIdx.x * 64;
    const int rloc = 16 * w + g;

    const uint32_t bRow = (uint32_t)(((lane >> 4) & 1) * 8 + (lane & 7)) * KP +
                          ((lane >> 3) & 1) * 16;

    const __nv_bfloat16* gsrc[4] = {
        g_Kh  + (size_t)bh * SEQ * DK,
        g_Kl  + (size_t)bh * SEQ * DK,
        g_Vth + (size_t)bh * DK * SEQ,
        g_Vtl + (size_t)bh * DK * SEQ };

    auto issue_f = [&](int jt) {
        const uint32_t buf = fb + (jt & 1) * FBUF;
        const int j0 = jt * 64;
        #pragma unroll
        for (int a = 0; a < 4; a++) {
            const size_t rstride = (a < 2) ? DK : SEQ;
            const size_t off = (a < 2) ? (size_t)j0 * DK : (size_t)j0;
            #pragma unroll
            for (int i = 0; i < 4; i++) {
                int id = tid + i * 128;
                int row = id >> 3, c8 = id & 7;
                cp_async16(buf + a * FARR + row * KP + c8 * 16,
                           gsrc[a] + off + (size_t)row * rstride + c8 * 8);
            }
        }
        cp_commit();
    };

    uint32_t qh[4][4], ql[4][4];
    {
        const size_t base = ((size_t)bh * SEQ + i0 + rloc) * DK;
        #pragma unroll
        for (int ks = 0; ks < 4; ks++) {
            size_t e = base + ks * 16 + 2 * q;
            qh[ks][0] = *(const uint32_t*)(g_Qh + e);
            qh[ks][1] = *(const uint32_t*)(g_Qh + e + 8 * DK);
            qh[ks][2] = *(const uint32_t*)(g_Qh + e + 8);
            qh[ks][3] = *(const uint32_t*)(g_Qh + e + 8 * DK + 8);
            ql[ks][0] = *(const uint32_t*)(g_Ql + e);
            ql[ks][1] = *(const uint32_t*)(g_Ql + e + 8 * DK);
            ql[ks][2] = *(const uint32_t*)(g_Ql + e + 8);
            ql[ks][3] = *(const uint32_t*)(g_Ql + e + 8 * DK + 8);
        }
    }

    float o[8][4] = {};
    float m0 = -1e30f, m1 = -1e30f, l0 = 0.f, l1 = 0.f;

    const int jmax = blockIdx.x;
    issue_f(0);
    #pragma unroll 1
    for (int jt = 0; jt <= jmax; jt++) {
        if (jt > 0) __syncthreads();          // all warps done reading buf[(jt+1)&1]
        if (jt < jmax) { issue_f(jt + 1); cp_wait<1>(); }
        else           { cp_wait<0>(); }
        __syncthreads();                      // buf[jt&1] complete + visible

        const uint32_t buf = fb + (jt & 1) * FBUF;
        const uint32_t kBaseH = buf + bRow;
        const uint32_t kBaseL = buf + FARR + bRow;
        const uint32_t vBaseH = buf + 2 * FARR + bRow;
        const uint32_t vBaseL = buf + 3 * FARR + bRow;

        // S = Qh*Kh + Qh*Kl + Ql*Kh
        float s[8][4];
        #pragma unroll
        for (int an = 0; an < 8; an++)
            s[an][0] = s[an][1] = s[an][2] = s[an][3] = 0.f;
        #pragma unroll
        for (int ks = 0; ks < 4; ks++) {
            #pragma unroll
            for (int j = 0; j < 4; j++) {
                uint32_t kh4[4], kl4[4];
                const uint32_t off = (uint32_t)j * 16 * KP + ks * 32;
                ldsm_x4(kh4, kBaseH + off);
                ldsm_x4(kl4, kBaseL + off);
                mma_bf16(s[2 * j],     qh[ks], &kh4[0]);
                mma_bf16(s[2 * j],     qh[ks], &kl4[0]);
                mma_bf16(s[2 * j],     ql[ks], &kh4[0]);
                mma_bf16(s[2 * j + 1], qh[ks], &kh4[2]);
                mma_bf16(s[2 * j + 1], qh[ks], &kl4[2]);
                mma_bf16(s[2 * j + 1], ql[ks], &kh4[2]);
            }
        }

        if (jt == jmax) {
            #pragma unroll
            for (int an = 0; an < 8; an++) {
                int c0 = an * 8 + 2 * q, c1 = c0 + 1;
                if (c0 > rloc)     s[an][0] = -1e9f;
                if (c1 > rloc)     s[an][1] = -1e9f;
                if (c0 > rloc + 8) s[an][2] = -1e9f;
                if (c1 > rloc + 8) s[an][3] = -1e9f;
            }
        }

        float mx0 = -1e30f, mx1 = -1e30f;
        #pragma unroll
        for (int an = 0; an < 8; an++) {
            mx0 = fmaxf(mx0, fmaxf(s[an][0], s[an][1]));
            mx1 = fmaxf(mx1, fmaxf(s[an][2], s[an][3]));
        }
        mx0 = fmaxf(mx0, __shfl_xor_sync(0xFFFFFFFF, mx0, 1));
        mx0 = fmaxf(mx0, __shfl_xor_sync(0xFFFFFFFF, mx0, 2));
        mx1 = fmaxf(mx1, __shfl_xor_sync(0xFFFFFFFF, mx1, 1));
        mx1 = fmaxf(mx1, __shfl_xor_sync(0xFFFFFFFF, mx1, 2));
        float mn0 = fmaxf(m0, mx0), mn1 = fmaxf(m1, mx1);
        float a0 = __expf(m0 - mn0), a1 = __expf(m1 - mn1);
        float sum0 = 0.f, sum1 = 0.f;
        #pragma unroll
        for (int an = 0; an < 8; an++) {
            s[an][0] = __expf(s[an][0] - mn0);
            s[an][1] = __expf(s[an][1] - mn0);
            s[an][2] = __expf(s[an][2] - mn1);
            s[an][3] = __expf(s[an][3] - mn1);
            sum0 += s[an][0] + s[an][1];
            sum1 += s[an][2] + s[an][3];
        }
        sum0 += __shfl_xor_sync(0xFFFFFFFF, sum0, 1);
        sum0 += __shfl_xor_sync(0xFFFFFFFF, sum0, 2);
        sum1 += __shfl_xor_sync(0xFFFFFFFF, sum1, 1);
        sum1 += __shfl_xor_sync(0xFFFFFFFF, sum1, 2);
        l0 = l0 * a0 + sum0;  l1 = l1 * a1 + sum1;
        m0 = mn0;  m1 = mn1;
        #pragma unroll
        for (int an = 0; an < 8; an++) {
            o[an][0] *= a0; o[an][1] *= a0;
            o[an][2] *= a1; o[an][3] *= a1;
        }

        uint32_t ph[4][4], pl[4][4];
        #pragma unroll
        for (int kb = 0; kb < 4; kb++) {
            split2(s[2 * kb][0],     s[2 * kb][1],     ph[kb][0], pl[kb][0]);
            split2(s[2 * kb][2],     s[2 * kb][3],     ph[kb][1], pl[kb][1]);
            split2(s[2 * kb + 1][0], s[2 * kb + 1][1], ph[kb][2], pl[kb][2]);
            split2(s[2 * kb + 1][2], s[2 * kb + 1][3], ph[kb][3], pl[kb][3]);
        }

        // O += Ph*Vh + Ph*Vl + Pl*Vh
        #pragma unroll
        for (int kb = 0; kb < 4; kb++) {
            #pragma unroll
            for (int j = 0; j < 4; j++) {
                uint32_t vh4[4], vl4[4];
                const uint32_t off = (uint32_t)j * 16 * KP + kb * 32;
                ldsm_x4(vh4, vBaseH + off);
                ldsm_x4(vl4, vBaseL + off);
                mma_bf16(o[2 * j],     ph[kb], &vh4[0]);
                mma_bf16(o[2 * j],     ph[kb], &vl4[0]);
                mma_bf16(o[2 * j],     pl[kb], &vh4[0]);
                mma_bf16(o[2 * j + 1], ph[kb], &vh4[2]);
                mma_bf16(o[2 * j + 1], ph[kb], &vl4[2]);
                mma_bf16(o[2 * j + 1], pl[kb], &vh4[2]);
            }
        }
    }

    const float li0 = 1.f / l0, li1 = 1.f / l1;
    const size_t row0 = (size_t)b * SEQ + i0 + rloc;
    #pragma unroll
    for (int an = 0; an < 8; an++) {
        const int col = h * DK + an * 8 + 2 * q;
        uint32_t hi, lo;
        split2(o[an][0] * li0, o[an][1] * li0, hi, lo);
        *(uint32_t*)(g_A_hi + row0 * D_MODEL + col) = hi;
        *(uint32_t*)(g_A_lo + row0 * D_MODEL + col) = lo;
        split2(o[an][2] * li1, o[an][3] * li1, hi, lo);
        *(uint32_t*)(g_A_hi + (row0 + 8) * D_MODEL + col) = hi;
        *(uint32_t*)(g_A_lo + (row0 + 8) * D_MODEL + col) = lo;
    }
}

// ---------------------------------------------------------------------------
extern "C" void kernel_launch(void* const* d_in, const int* in_sizes, int n_in,
                              void* d_out, int out_size)
{
    const float* x     = (const float*)d_in[0];
    const float* Wqkv  = (const float*)d_in[1];
    const float* Wproj = (const float*)d_in[2];
    float* out = (float*)d_out;

    const int GEMM_SMEM  = 2 * BUFSZ;   // 80 KB
    const int FLASH_SMEM = 2 * FBUF;    // 72 KB
    cudaFuncSetAttribute(mma_gemm<true>,
                         cudaFuncAttributeMaxDynamicSharedMemorySize, GEMM_SMEM);
    cudaFuncSetAttribute(mma_gemm<false>,
                         cudaFuncAttributeMaxDynamicSharedMemorySize, GEMM_SMEM);
    cudaFuncSetAttribute(flash_mma,
                         cudaFuncAttributeMaxDynamicSharedMemorySize, FLASH_SMEM);

    // weight prepasses
    wprep_kernel<0><<<dim3(3 * D_MODEL / 32, D_MODEL / 32), dim3(32, 8)>>>(Wqkv, 3 * D_MODEL);
    wprep_kernel<1><<<dim3(D_MODEL / 32, D_MODEL / 32), dim3(32, 8)>>>(Wproj, D_MODEL);

    // x -> hi/lo
    aprep_kernel<<<(size_t)MTOT * D_MODEL / 4 / 256, 256>>>(x);

    // qkv GEMM with fused split epilogue -> g_Qh/Ql, g_Kh/Kl, g_Vh/Vl
    mma_gemm<true><<<dim3(3 * D_MODEL / 128, MTOT / 128), 256, GEMM_SMEM>>>(nullptr);

    // V transpose for flash B-operand layout
    vtrans_kernel<<<dim3(SEQ / 64, BH), 256>>>();

    // tensor-core flash attention -> writes g_A_hi/g_A_lo directly
    flash_mma<<<dim3(SEQ / 64, BH), 128, FLASH_SMEM>>>();

    // out = attn @ W_proj
    mma_gemm<false><<<dim3(D_MODEL / 128, MTOT / 128), 256, GEMM_SMEM>>>(out);
}